// round 10
// baseline (speedup 1.0000x reference)
#include <cuda_runtime.h>
#include <cuda_fp16.h>
#include <math.h>
#include <stdint.h>

// ---------------------------------------------------------------------------
// TidalTransformer: B=4, S=1024, H=1024, NH=16, DK=64, DF=4096, L=4, V=32000
// Round 10: 128-row Q-tile attention (1-wave, reversed schedule), merged
//           weight prep, fp16 GEMMs (M-fastest grid), fused LN.
// ---------------------------------------------------------------------------

#define Bz   4
#define Sz   1024
#define Hz   1024
#define NHz  16
#define DKz  64
#define DFz  4096
#define Lz   4
#define Vz   32000
#define Mz   (Bz * Sz)
#define QKVN 3072

// ------------------------- scratch (device globals) ------------------------
__device__ float  g_x   [(size_t)Mz * Hz];
__device__ __half g_xch [(size_t)Mz * Hz];
__device__ __half g_qkv [(size_t)Mz * QKVN];
__device__ __half g_attnc[(size_t)Mz * Hz];
__device__ float  g_tmp [(size_t)Mz * Hz];
__device__ __half g_ffc [(size_t)Mz * DFz];

#define OFF_QKV 0
#define OFF_WO  ((size_t)12582912)
#define OFF_W1  ((size_t)16777216)
#define OFF_W2  ((size_t)33554432)
#define OFF_WF  ((size_t)50331648)
__device__ __half g_w[(size_t)83099648];
__device__ float  g_bqkv[Lz * QKVN];

// ----------------------- merged weight prep --------------------------------
// One launch transposing every weight matrix [K,N]fp32 -> [N,K]fp16.
// Tile ranges: Wq[0,4096) Wk[4096,8192) Wv[8192,12288) Wo[12288,16384)
//              W1[16384,32768) W2[32768,49152) Wf[49152,81152)
#define PREP_TILES 81152

__global__ void prep_all_kernel(const float* __restrict__ Wq, const float* __restrict__ Wk,
                                const float* __restrict__ Wv, const float* __restrict__ Wo,
                                const float* __restrict__ W1, const float* __restrict__ W2,
                                const float* __restrict__ Wf, __half* __restrict__ w)
{
    __shared__ float t[32][33];
    int idx = blockIdx.x;
    const float* src;
    __half* dst;
    int K, N;

    if (idx < 4096) {
        int l = idx >> 10; idx &= 1023;
        src = Wq + (size_t)l * Hz * Hz; dst = w + OFF_QKV + (size_t)l * Hz * QKVN;
        K = Hz; N = Hz;
    } else if (idx < 8192) {
        idx -= 4096; int l = idx >> 10; idx &= 1023;
        src = Wk + (size_t)l * Hz * Hz;
        dst = w + OFF_QKV + (size_t)l * Hz * QKVN + (size_t)1024 * Hz;
        K = Hz; N = Hz;
    } else if (idx < 12288) {
        idx -= 8192; int l = idx >> 10; idx &= 1023;
        src = Wv + (size_t)l * Hz * Hz;
        dst = w + OFF_QKV + (size_t)l * Hz * QKVN + (size_t)2048 * Hz;
        K = Hz; N = Hz;
    } else if (idx < 16384) {
        idx -= 12288; int l = idx >> 10; idx &= 1023;
        src = Wo + (size_t)l * Hz * Hz; dst = w + OFF_WO + (size_t)l * Hz * Hz;
        K = Hz; N = Hz;
    } else if (idx < 32768) {
        idx -= 16384; int l = idx >> 12; idx &= 4095;
        src = W1 + (size_t)l * Hz * DFz; dst = w + OFF_W1 + (size_t)l * Hz * DFz;
        K = Hz; N = DFz;
    } else if (idx < 49152) {
        idx -= 32768; int l = idx >> 12; idx &= 4095;
        src = W2 + (size_t)l * DFz * Hz; dst = w + OFF_W2 + (size_t)l * DFz * Hz;
        K = DFz; N = Hz;
    } else {
        idx -= 49152;
        src = Wf; dst = w + OFF_WF;
        K = Hz; N = Vz;
    }

    int nt = N >> 5;
    int kb = (idx / nt) * 32, nb = (idx % nt) * 32;
    int tx = threadIdx.x, ty = threadIdx.y;
    #pragma unroll
    for (int i = 0; i < 4; i++)
        t[ty + i * 8][tx] = src[(size_t)(kb + ty + i * 8) * N + nb + tx];
    __syncthreads();
    #pragma unroll
    for (int i = 0; i < 4; i++)
        dst[(size_t)(nb + ty + i * 8) * K + kb + tx] = __float2half_rn(t[tx][ty + i * 8]);
}

__global__ void cvt_bias_kernel(const float* __restrict__ bq, const float* __restrict__ bk,
                                const float* __restrict__ bv, float* __restrict__ dst)
{
    int i = blockIdx.x * 256 + threadIdx.x;
    int n = i % QKVN, l = i / QKVN;
    float v;
    if (n < 1024)       v = bq[l * 1024 + n];
    else if (n < 2048)  v = bk[l * 1024 + n - 1024];
    else                v = bv[l * 1024 + n - 2048];
    dst[i] = v;
}

// ------------------------------- embedding ---------------------------------
__global__ void embed_kernel(const int* __restrict__ ids,
                             const float* __restrict__ emb,
                             float* __restrict__ x, __half* __restrict__ xch)
{
    int row = blockIdx.x;
    int tid = threadIdx.x;
    int id  = ids[row];
    float4 v = *(const float4*)(emb + (size_t)id * Hz + tid * 4);
    v.x *= 32.0f; v.y *= 32.0f; v.z *= 32.0f; v.w *= 32.0f;
    *(float4*)(x + (size_t)row * Hz + tid * 4) = v;
    *(__half2*)(xch + (size_t)row * Hz + tid * 4)     = __floats2half2_rn(v.x, v.y);
    *(__half2*)(xch + (size_t)row * Hz + tid * 4 + 2) = __floats2half2_rn(v.z, v.w);
}

// ---------------------------- mma / ldmatrix -------------------------------
__device__ __forceinline__ void mmah(float* c, const uint32_t* a, const uint32_t* b) {
    asm volatile(
        "mma.sync.aligned.m16n8k16.row.col.f32.f16.f16.f32 "
        "{%0,%1,%2,%3},{%4,%5,%6,%7},{%8,%9},{%0,%1,%2,%3};"
        : "+f"(c[0]), "+f"(c[1]), "+f"(c[2]), "+f"(c[3])
        : "r"(a[0]), "r"(a[1]), "r"(a[2]), "r"(a[3]), "r"(b[0]), "r"(b[1]));
}
__device__ __forceinline__ void ldsm4(uint32_t addr, uint32_t& r0, uint32_t& r1,
                                      uint32_t& r2, uint32_t& r3) {
    asm volatile("ldmatrix.sync.aligned.m8n8.x4.shared.b16 {%0,%1,%2,%3}, [%4];"
                 : "=r"(r0), "=r"(r1), "=r"(r2), "=r"(r3) : "r"(addr));
}
__device__ __forceinline__ void cpasync16(uint32_t dst, const void* src) {
    asm volatile("cp.async.cg.shared.global [%0], [%1], 16;" :: "r"(dst), "l"(src));
}

// ------------------ fp16 GEMM: 128x128 tile, BK=64, 3-stage ----------------
#define HSTR 72
#define TILE_H (128 * HSTR)
#define GEMM_SMEM (6 * TILE_H * 2)

__global__ __launch_bounds__(256, 2)
void gemm_h_kernel(const __half* __restrict__ A, const __half* __restrict__ Wt,
                   const float* __restrict__ bias, void* __restrict__ Cv,
                   int M, int N, int K, int op, const int* __restrict__ start_pos)
{
    extern __shared__ __half hsm[];
    int tid = threadIdx.x, lane = tid & 31, warp = tid >> 5;
    int wm = warp & 1, wn = warp >> 1;
    int m0 = blockIdx.x * 128, n0 = blockIdx.y * 128;

    int crow = tid >> 1;
    int cc16 = (tid & 1) * 4;
    const __half* aSrc = A  + (size_t)(m0 + crow) * K + cc16 * 8;
    const __half* bSrc = Wt + (size_t)(n0 + crow) * K + cc16 * 8;
    uint32_t asBase = (uint32_t)__cvta_generic_to_shared(hsm);
    uint32_t bsBase = asBase + 3 * TILE_H * 2;
    uint32_t cOff = (uint32_t)(crow * 144 + cc16 * 16);

    float acc[4][4][4];
    #pragma unroll
    for (int i = 0; i < 4; i++)
        #pragma unroll
        for (int j = 0; j < 4; j++)
            #pragma unroll
            for (int r = 0; r < 4; r++) acc[i][j][r] = 0.f;

    int KT = K >> 6;

    #pragma unroll
    for (int s = 0; s < 2; s++) {
        int kk = s * 64;
        #pragma unroll
        for (int i = 0; i < 4; i++)
            cpasync16(asBase + s * (TILE_H * 2) + cOff + i * 16, aSrc + kk + i * 8);
        #pragma unroll
        for (int i = 0; i < 4; i++)
            cpasync16(bsBase + s * (TILE_H * 2) + cOff + i * 16, bSrc + kk + i * 8);
        asm volatile("cp.async.commit_group;");
    }

    uint32_t aLd = (uint32_t)((wm * 64 + (lane & 15)) * 144 + (lane >> 4) * 16);
    uint32_t bLd = (uint32_t)((wn * 32 + (lane & 15)) * 144 + (lane >> 4) * 16);

    for (int kt = 0; kt < KT; ++kt) {
        asm volatile("cp.async.wait_group 1;" ::: "memory");
        __syncthreads();

        if (kt + 2 < KT) {
            int s = (kt + 2) % 3;
            int kk = (kt + 2) * 64;
            #pragma unroll
            for (int i = 0; i < 4; i++)
                cpasync16(asBase + s * (TILE_H * 2) + cOff + i * 16, aSrc + kk + i * 8);
            #pragma unroll
            for (int i = 0; i < 4; i++)
                cpasync16(bsBase + s * (TILE_H * 2) + cOff + i * 16, bSrc + kk + i * 8);
        }
        asm volatile("cp.async.commit_group;");

        uint32_t aSB = asBase + (kt % 3) * (TILE_H * 2);
        uint32_t bSB = bsBase + (kt % 3) * (TILE_H * 2);

        #pragma unroll
        for (int ks = 0; ks < 4; ++ks) {
            uint32_t afr[4][4], br[2][4];
            #pragma unroll
            for (int im = 0; im < 4; im++)
                ldsm4(aSB + aLd + im * 2304 + ks * 32,
                      afr[im][0], afr[im][1], afr[im][2], afr[im][3]);
            #pragma unroll
            for (int p = 0; p < 2; p++)
                ldsm4(bSB + bLd + p * 2304 + ks * 32,
                      br[p][0], br[p][1], br[p][2], br[p][3]);
            #pragma unroll
            for (int im = 0; im < 4; im++)
                #pragma unroll
                for (int in = 0; in < 4; in++) {
                    uint32_t bb[2] = { br[in >> 1][in & 1], br[in >> 1][(in & 1) + 2] };
                    mmah(acc[im][in], afr[im], bb);
                }
        }
    }

    int rbase = m0 + wm * 64 + (lane >> 2);
    int cbase = n0 + wn * 32 + ((lane & 3) << 1);
    #pragma unroll
    for (int im = 0; im < 4; im++) {
        #pragma unroll
        for (int hh = 0; hh < 2; hh++) {
            int row = rbase + im * 16 + hh * 8;
            bool zero = false;
            if (op == 2) zero = (row & 1023) < start_pos[row >> 10];
            #pragma unroll
            for (int in = 0; in < 4; in++) {
                int col = cbase + in * 8;
                float v0 = acc[im][in][hh * 2 + 0] + bias[col];
                float v1 = acc[im][in][hh * 2 + 1] + bias[col + 1];
                if (op == 1) {
                    v0 = 0.5f * v0 * (1.0f + erff(v0 * 0.70710678118654752f));
                    v1 = 0.5f * v1 * (1.0f + erff(v1 * 0.70710678118654752f));
                }
                if (op == 0 || op == 1) {
                    *(__half2*)((__half*)Cv + (size_t)row * N + col) =
                        __floats2half2_rn(v0, v1);
                } else {
                    if (zero) { v0 = 0.f; v1 = 0.f; }
                    float2 o; o.x = v0; o.y = v1;
                    *(float2*)((float*)Cv + (size_t)row * N + col) = o;
                }
            }
        }
    }
}

// ------------- fp16 flash attention: 128-row Q tile, 8 warps ---------------
#define AH 72
// smem halves: sQ 128*AH, sK 64*AH, sVt 64*AH, sP 128*AH
#define ATTN_SMEM ((128 + 64 + 64 + 128) * AH * 2)

__global__ __launch_bounds__(256)
void attn_h_kernel(const __half* __restrict__ QKV, __half* __restrict__ O,
                   const int* __restrict__ start_pos)
{
    extern __shared__ __half asm_[];
    __half* sQ  = asm_;
    __half* sK  = sQ + 128 * AH;
    __half* sVt = sK + 64 * AH;
    __half* sP  = sVt + 64 * AH;
    uint32_t* pW = (uint32_t*)sP;

    int tid = threadIdx.x, lane = tid & 31, warp = tid >> 5;
    int qt = (int)(gridDim.x - 1 - blockIdx.x);   // heavy tiles first
    int bh = blockIdx.y;
    int b = bh >> 4, h = bh & 15;
    int sp = start_pos[b];
    float slope = exp2f(-0.5f * (float)(h + 1));
    int brow = b * Sz;

    const __half* Qg = QKV + h * 64;
    const __half* Kg = QKV + 1024 + h * 64;
    const __half* Vg = QKV + 2048 + h * 64;

    uint32_t sQb = (uint32_t)__cvta_generic_to_shared(sQ);
    uint32_t sKb = (uint32_t)__cvta_generic_to_shared(sK);
    uint32_t sVb = (uint32_t)__cvta_generic_to_shared(sVt);
    uint32_t sPb = (uint32_t)__cvta_generic_to_shared(sP);

    const __half2 hscale = __float2half2_rn(0.125f);
    for (int i = tid; i < 128 * 16; i += 256) {
        int row = i >> 4, d4 = (i & 15) * 4;
        uint2 u = *(const uint2*)(Qg + (size_t)(brow + qt * 128 + row) * QKVN + d4);
        __half2 h0 = __hmul2(*(__half2*)&u.x, hscale);
        __half2 h1 = __hmul2(*(__half2*)&u.y, hscale);
        uint2 o; o.x = *(uint32_t*)&h0; o.y = *(uint32_t*)&h1;
        *(uint2*)(sQ + row * AH + d4) = o;
    }

    int qrow = warp * 16 + (lane >> 2);          // 0..127
    int cA   = lane & 3;
    int ig0 = qt * 128 + qrow, ig1 = ig0 + 8;

    uint32_t fragQ = (uint32_t)((warp * 16 + (lane & 15)) * 144 + (lane >> 4) * 16);
    uint32_t fragB = (uint32_t)((lane & 15) * 144 + (lane >> 4) * 16);

    float m0 = -1e30f, m1 = -1e30f, l0 = 0.f, l1 = 0.f;
    float oacc[8][4];
    #pragma unroll
    for (int n = 0; n < 8; n++)
        #pragma unroll
        for (int r = 0; r < 4; r++) oacc[n][r] = 0.f;

    int ktmax = (qt * 128 >= sp) ? (2 * qt + 1) : 15;

    for (int kt = 0; kt <= ktmax; ++kt) {
        __syncthreads();
        for (int i = tid; i < 64 * 16; i += 256) {
            int row = i >> 4, d4 = (i & 15) * 4;
            uint2 uk = *(const uint2*)(Kg + (size_t)(brow + kt * 64 + row) * QKVN + d4);
            *(uint2*)(sK + row * AH + d4) = uk;
            uint2 uv = *(const uint2*)(Vg + (size_t)(brow + kt * 64 + row) * QKVN + d4);
            __half vh[4];
            *(uint2*)vh = uv;
            #pragma unroll
            for (int j = 0; j < 4; j++)
                sVt[(d4 + j) * AH + row] = vh[j];
        }
        __syncthreads();

        // ---- scores = Q @ K^T ----
        float sacc[8][4];
        #pragma unroll
        for (int n = 0; n < 8; n++)
            #pragma unroll
            for (int r = 0; r < 4; r++) sacc[n][r] = 0.f;

        #pragma unroll
        for (int ks = 0; ks < 4; ++ks) {
            uint32_t af[4], br[4][4];
            ldsm4(sQb + fragQ + ks * 32, af[0], af[1], af[2], af[3]);
            #pragma unroll
            for (int p = 0; p < 4; p++)
                ldsm4(sKb + fragB + p * 2304 + ks * 32,
                      br[p][0], br[p][1], br[p][2], br[p][3]);
            #pragma unroll
            for (int n = 0; n < 8; n++) {
                uint32_t bb[2] = { br[n >> 1][n & 1], br[n >> 1][(n & 1) + 2] };
                mmah(sacc[n], af, bb);
            }
        }

        // ---- alibi + mask ----
        #pragma unroll
        for (int n = 0; n < 8; n++) {
            int jg = kt * 64 + n * 8 + cA * 2;
            #pragma unroll
            for (int half = 0; half < 2; half++) {
                int j = jg + half;
                float al = slope * (float)(j - sp);
                bool ok0 = (j <= ig0) || (ig0 < sp) || (j < sp);
                bool ok1 = (j <= ig1) || (ig1 < sp) || (j < sp);
                sacc[n][half]     = ok0 ? sacc[n][half]     + al : -1e30f;
                sacc[n][half + 2] = ok1 ? sacc[n][half + 2] + al : -1e30f;
            }
        }

        // ---- row max ----
        float t0 = -1e30f, t1 = -1e30f;
        #pragma unroll
        for (int n = 0; n < 8; n++) {
            t0 = fmaxf(t0, fmaxf(sacc[n][0], sacc[n][1]));
            t1 = fmaxf(t1, fmaxf(sacc[n][2], sacc[n][3]));
        }
        t0 = fmaxf(t0, __shfl_xor_sync(0xffffffffu, t0, 1));
        t0 = fmaxf(t0, __shfl_xor_sync(0xffffffffu, t0, 2));
        t1 = fmaxf(t1, __shfl_xor_sync(0xffffffffu, t1, 1));
        t1 = fmaxf(t1, __shfl_xor_sync(0xffffffffu, t1, 2));

        float mn0 = fmaxf(m0, t0), mn1 = fmaxf(m1, t1);
        float scl0 = __expf(m0 - mn0), scl1 = __expf(m1 - mn1);
        m0 = mn0; m1 = mn1;

        float ls0 = 0.f, ls1 = 0.f;
        #pragma unroll
        for (int n = 0; n < 8; n++) {
            __half2 hp0 = __floats2half2_rn(__expf(sacc[n][0] - mn0),
                                            __expf(sacc[n][1] - mn0));
            __half2 hp1 = __floats2half2_rn(__expf(sacc[n][2] - mn1),
                                            __expf(sacc[n][3] - mn1));
            float2 f0 = __half22float2(hp0);
            float2 f1 = __half22float2(hp1);
            ls0 += f0.x + f0.y;
            ls1 += f1.x + f1.y;
            pW[(qrow)     * 36 + n * 4 + cA] = *(uint32_t*)&hp0;
            pW[(qrow + 8) * 36 + n * 4 + cA] = *(uint32_t*)&hp1;
        }
        ls0 += __shfl_xor_sync(0xffffffffu, ls0, 1);
        ls0 += __shfl_xor_sync(0xffffffffu, ls0, 2);
        ls1 += __shfl_xor_sync(0xffffffffu, ls1, 1);
        ls1 += __shfl_xor_sync(0xffffffffu, ls1, 2);
        l0 = l0 * scl0 + ls0;
        l1 = l1 * scl1 + ls1;

        #pragma unroll
        for (int n = 0; n < 8; n++) {
            oacc[n][0] *= scl0; oacc[n][1] *= scl0;
            oacc[n][2] *= scl1; oacc[n][3] *= scl1;
        }
        __syncwarp();

        // ---- O += P @ V ----
        #pragma unroll
        for (int ks = 0; ks < 4; ++ks) {
            uint32_t af[4], br[4][4];
            ldsm4(sPb + fragQ + ks * 32, af[0], af[1], af[2], af[3]);
            #pragma unroll
            for (int p = 0; p < 4; p++)
                ldsm4(sVb + fragB + p * 2304 + ks * 32,
                      br[p][0], br[p][1], br[p][2], br[p][3]);
            #pragma unroll
            for (int n = 0; n < 8; n++) {
                uint32_t bb[2] = { br[n >> 1][n & 1], br[n >> 1][(n & 1) + 2] };
                mmah(oacc[n], af, bb);
            }
        }
        __syncwarp();
    }

    float inv0 = 1.f / l0, inv1 = 1.f / l1;
    size_t orow0 = (size_t)(brow + qt * 128 + qrow) * Hz + h * 64;
    size_t orow1 = orow0 + (size_t)8 * Hz;
    #pragma unroll
    for (int n = 0; n < 8; n++) {
        int col = n * 8 + cA * 2;
        *(__half2*)(O + orow0 + col) = __floats2half2_rn(oacc[n][0] * inv0, oacc[n][1] * inv0);
        *(__half2*)(O + orow1 + col) = __floats2half2_rn(oacc[n][2] * inv1, oacc[n][3] * inv1);
    }
}

// ------------------------ fused residual + layernorm -----------------------
__inline__ __device__ float warp_sum(float v) {
    #pragma unroll
    for (int o = 16; o; o >>= 1) v += __shfl_xor_sync(0xffffffffu, v, o);
    return v;
}

__global__ void add_ln_kernel(float* __restrict__ x, __half* __restrict__ xch,
                              const float* __restrict__ t,
                              const float* __restrict__ g, const float* __restrict__ b)
{
    int row = blockIdx.x;
    int tid = threadIdx.x;
    size_t off = (size_t)row * Hz + tid * 4;

    float4 xv = *(const float4*)(x + off);
    float4 tv = *(const float4*)(t + off);
    float v0 = xv.x + tv.x, v1 = xv.y + tv.y, v2 = xv.z + tv.z, v3 = xv.w + tv.w;

    float s  = v0 + v1 + v2 + v3;
    float s2 = v0 * v0 + v1 * v1 + v2 * v2 + v3 * v3;

    __shared__ float sh1[8], sh2[8];
    int lane = tid & 31, wid = tid >> 5;
    s  = warp_sum(s);
    s2 = warp_sum(s2);
    if (lane == 0) { sh1[wid] = s; sh2[wid] = s2; }
    __syncthreads();
    if (wid == 0) {
        float a = (lane < 8) ? sh1[lane] : 0.f;
        float c = (lane < 8) ? sh2[lane] : 0.f;
        a = warp_sum(a);
        c = warp_sum(c);
        if (lane == 0) { sh1[0] = a; sh2[0] = c; }
    }
    __syncthreads();

    float mu  = sh1[0] * (1.0f / Hz);
    float var = sh2[0] * (1.0f / Hz) - mu * mu;
    float inv = rsqrtf(var + 1e-5f);

    int cbase = tid * 4;
    float4 gv = *(const float4*)(g + cbase);
    float4 bv = *(const float4*)(b + cbase);
    float4 out;
    out.x = (v0 - mu) * inv * gv.x + bv.x;
    out.y = (v1 - mu) * inv * gv.y + bv.y;
    out.z = (v2 - mu) * inv * gv.z + bv.z;
    out.w = (v3 - mu) * inv * gv.w + bv.w;
    *(float4*)(x + off) = out;
    *(__half2*)(xch + off)     = __floats2half2_rn(out.x, out.y);
    *(__half2*)(xch + off + 2) = __floats2half2_rn(out.z, out.w);
}

// --------------------------------- launch ----------------------------------
extern "C" void kernel_launch(void* const* d_in, const int* in_sizes, int n_in,
                              void* d_out, int out_size)
{
    const int*   ids  = (const int*)d_in[0];
    const int*   sp   = (const int*)d_in[1];
    const float* emb  = (const float*)d_in[2];
    const float* Wq   = (const float*)d_in[3];
    const float* bq   = (const float*)d_in[4];
    const float* Wk   = (const float*)d_in[5];
    const float* bk   = (const float*)d_in[6];
    const float* Wv   = (const float*)d_in[7];
    const float* bv   = (const float*)d_in[8];
    const float* Wo   = (const float*)d_in[9];
    const float* bo   = (const float*)d_in[10];
    const float* ln1g = (const float*)d_in[11];
    const float* ln1b = (const float*)d_in[12];
    const float* ln2g = (const float*)d_in[13];
    const float* ln2b = (const float*)d_in[14];
    const float* W1   = (const float*)d_in[15];
    const float* b1   = (const float*)d_in[16];
    const float* W2   = (const float*)d_in[17];
    const float* b2   = (const float*)d_in[18];
    const float* Wf   = (const float*)d_in[19];
    const float* bf   = (const float*)d_in[20];
    float* out = (float*)d_out;

    float *x, *tmp, *bqkv;
    __half *xch, *qkv, *attnc, *ffc, *w;
    cudaGetSymbolAddress((void**)&x,     g_x);
    cudaGetSymbolAddress((void**)&xch,   g_xch);
    cudaGetSymbolAddress((void**)&qkv,   g_qkv);
    cudaGetSymbolAddress((void**)&attnc, g_attnc);
    cudaGetSymbolAddress((void**)&tmp,   g_tmp);
    cudaGetSymbolAddress((void**)&ffc,   g_ffc);
    cudaGetSymbolAddress((void**)&w,     g_w);
    cudaGetSymbolAddress((void**)&bqkv,  g_bqkv);

    cudaFuncSetAttribute(gemm_h_kernel, cudaFuncAttributeMaxDynamicSharedMemorySize, GEMM_SMEM);
    cudaFuncSetAttribute(attn_h_kernel, cudaFuncAttributeMaxDynamicSharedMemorySize, ATTN_SMEM);

    prep_all_kernel<<<PREP_TILES, dim3(32, 8)>>>(Wq, Wk, Wv, Wo, W1, W2, Wf, w);
    cvt_bias_kernel<<<(Lz * QKVN) / 256, 256>>>(bq, bk, bv, bqkv);
    embed_kernel<<<Mz, 256>>>(ids, emb, x, xch);

    for (int l = 0; l < Lz; ++l) {
        gemm_h_kernel<<<dim3(Mz / 128, QKVN / 128), 256, GEMM_SMEM>>>(
            xch, w + OFF_QKV + (size_t)l * Hz * QKVN, bqkv + l * QKVN, qkv,
            Mz, QKVN, Hz, 0, sp);

        attn_h_kernel<<<dim3(Sz / 128, Bz * NHz), 256, ATTN_SMEM>>>(qkv, attnc, sp);

        gemm_h_kernel<<<dim3(Mz / 128, Hz / 128), 256, GEMM_SMEM>>>(
            attnc, w + OFF_WO + (size_t)l * Hz * Hz, bo + l * Hz, tmp,
            Mz, Hz, Hz, 3, sp);
        add_ln_kernel<<<Mz, 256>>>(x, xch, tmp, ln1g + l * Hz, ln1b + l * Hz);

        gemm_h_kernel<<<dim3(Mz / 128, DFz / 128), 256, GEMM_SMEM>>>(
            xch, w + OFF_W1 + (size_t)l * Hz * DFz, b1 + l * DFz, ffc,
            Mz, DFz, Hz, 1, sp);
        gemm_h_kernel<<<dim3(Mz / 128, Hz / 128), 256, GEMM_SMEM>>>(
            ffc, w + OFF_W2 + (size_t)l * DFz * Hz, b2 + l * Hz, tmp,
            Mz, Hz, DFz, 3, sp);
        add_ln_kernel<<<Mz, 256>>>(x, xch, tmp, ln2g + l * Hz, ln2b + l * Hz);
    }

    gemm_h_kernel<<<dim3(Mz / 128, Vz / 128), 256, GEMM_SMEM>>>(
        xch, w + OFF_WF, bf, out, Mz, Vz, Hz, 2, sp);
}

// round 11
// speedup vs baseline: 1.0505x; 1.0505x over previous
#include <cuda_runtime.h>
#include <cuda_fp16.h>
#include <math.h>
#include <stdint.h>

// ---------------------------------------------------------------------------
// TidalTransformer: B=4, S=1024, H=1024, NH=16, DK=64, DF=4096, L=4, V=32000
// Round 11: R9 64-row attention + merged prep + GEMM copy-issue reorder.
// ---------------------------------------------------------------------------

#define Bz   4
#define Sz   1024
#define Hz   1024
#define NHz  16
#define DKz  64
#define DFz  4096
#define Lz   4
#define Vz   32000
#define Mz   (Bz * Sz)
#define QKVN 3072

// ------------------------- scratch (device globals) ------------------------
__device__ float  g_x   [(size_t)Mz * Hz];
__device__ __half g_xch [(size_t)Mz * Hz];
__device__ __half g_qkv [(size_t)Mz * QKVN];
__device__ __half g_attnc[(size_t)Mz * Hz];
__device__ float  g_tmp [(size_t)Mz * Hz];
__device__ __half g_ffc [(size_t)Mz * DFz];

#define OFF_QKV 0
#define OFF_WO  ((size_t)12582912)
#define OFF_W1  ((size_t)16777216)
#define OFF_W2  ((size_t)33554432)
#define OFF_WF  ((size_t)50331648)
__device__ __half g_w[(size_t)83099648];
__device__ float  g_bqkv[Lz * QKVN];

// ----------------------- merged weight prep --------------------------------
#define PREP_TILES 81152

__global__ void prep_all_kernel(const float* __restrict__ Wq, const float* __restrict__ Wk,
                                const float* __restrict__ Wv, const float* __restrict__ Wo,
                                const float* __restrict__ W1, const float* __restrict__ W2,
                                const float* __restrict__ Wf, __half* __restrict__ w)
{
    __shared__ float t[32][33];
    int idx = blockIdx.x;
    const float* src;
    __half* dst;
    int K, N;

    if (idx < 4096) {
        int l = idx >> 10; idx &= 1023;
        src = Wq + (size_t)l * Hz * Hz; dst = w + OFF_QKV + (size_t)l * Hz * QKVN;
        K = Hz; N = Hz;
    } else if (idx < 8192) {
        idx -= 4096; int l = idx >> 10; idx &= 1023;
        src = Wk + (size_t)l * Hz * Hz;
        dst = w + OFF_QKV + (size_t)l * Hz * QKVN + (size_t)1024 * Hz;
        K = Hz; N = Hz;
    } else if (idx < 12288) {
        idx -= 8192; int l = idx >> 10; idx &= 1023;
        src = Wv + (size_t)l * Hz * Hz;
        dst = w + OFF_QKV + (size_t)l * Hz * QKVN + (size_t)2048 * Hz;
        K = Hz; N = Hz;
    } else if (idx < 16384) {
        idx -= 12288; int l = idx >> 10; idx &= 1023;
        src = Wo + (size_t)l * Hz * Hz; dst = w + OFF_WO + (size_t)l * Hz * Hz;
        K = Hz; N = Hz;
    } else if (idx < 32768) {
        idx -= 16384; int l = idx >> 12; idx &= 4095;
        src = W1 + (size_t)l * Hz * DFz; dst = w + OFF_W1 + (size_t)l * Hz * DFz;
        K = Hz; N = DFz;
    } else if (idx < 49152) {
        idx -= 32768; int l = idx >> 12; idx &= 4095;
        src = W2 + (size_t)l * DFz * Hz; dst = w + OFF_W2 + (size_t)l * DFz * Hz;
        K = DFz; N = Hz;
    } else {
        idx -= 49152;
        src = Wf; dst = w + OFF_WF;
        K = Hz; N = Vz;
    }

    int nt = N >> 5;
    int kb = (idx / nt) * 32, nb = (idx % nt) * 32;
    int tx = threadIdx.x, ty = threadIdx.y;
    #pragma unroll
    for (int i = 0; i < 4; i++)
        t[ty + i * 8][tx] = src[(size_t)(kb + ty + i * 8) * N + nb + tx];
    __syncthreads();
    #pragma unroll
    for (int i = 0; i < 4; i++)
        dst[(size_t)(nb + ty + i * 8) * K + kb + tx] = __float2half_rn(t[tx][ty + i * 8]);
}

__global__ void cvt_bias_kernel(const float* __restrict__ bq, const float* __restrict__ bk,
                                const float* __restrict__ bv, float* __restrict__ dst)
{
    int i = blockIdx.x * 256 + threadIdx.x;
    int n = i % QKVN, l = i / QKVN;
    float v;
    if (n < 1024)       v = bq[l * 1024 + n];
    else if (n < 2048)  v = bk[l * 1024 + n - 1024];
    else                v = bv[l * 1024 + n - 2048];
    dst[i] = v;
}

// ------------------------------- embedding ---------------------------------
__global__ void embed_kernel(const int* __restrict__ ids,
                             const float* __restrict__ emb,
                             float* __restrict__ x, __half* __restrict__ xch)
{
    int row = blockIdx.x;
    int tid = threadIdx.x;
    int id  = ids[row];
    float4 v = *(const float4*)(emb + (size_t)id * Hz + tid * 4);
    v.x *= 32.0f; v.y *= 32.0f; v.z *= 32.0f; v.w *= 32.0f;
    *(float4*)(x + (size_t)row * Hz + tid * 4) = v;
    *(__half2*)(xch + (size_t)row * Hz + tid * 4)     = __floats2half2_rn(v.x, v.y);
    *(__half2*)(xch + (size_t)row * Hz + tid * 4 + 2) = __floats2half2_rn(v.z, v.w);
}

// ---------------------------- mma / ldmatrix -------------------------------
__device__ __forceinline__ void mmah(float* c, const uint32_t* a, const uint32_t* b) {
    asm volatile(
        "mma.sync.aligned.m16n8k16.row.col.f32.f16.f16.f32 "
        "{%0,%1,%2,%3},{%4,%5,%6,%7},{%8,%9},{%0,%1,%2,%3};"
        : "+f"(c[0]), "+f"(c[1]), "+f"(c[2]), "+f"(c[3])
        : "r"(a[0]), "r"(a[1]), "r"(a[2]), "r"(a[3]), "r"(b[0]), "r"(b[1]));
}
__device__ __forceinline__ void ldsm4(uint32_t addr, uint32_t& r0, uint32_t& r1,
                                      uint32_t& r2, uint32_t& r3) {
    asm volatile("ldmatrix.sync.aligned.m8n8.x4.shared.b16 {%0,%1,%2,%3}, [%4];"
                 : "=r"(r0), "=r"(r1), "=r"(r2), "=r"(r3) : "r"(addr));
}
__device__ __forceinline__ void cpasync16(uint32_t dst, const void* src) {
    asm volatile("cp.async.cg.shared.global [%0], [%1], 16;" :: "r"(dst), "l"(src));
}

// ------------------ fp16 GEMM: 128x128 tile, BK=64, 3-stage ----------------
#define HSTR 72
#define TILE_H (128 * HSTR)
#define GEMM_SMEM (6 * TILE_H * 2)

__global__ __launch_bounds__(256, 2)
void gemm_h_kernel(const __half* __restrict__ A, const __half* __restrict__ Wt,
                   const float* __restrict__ bias, void* __restrict__ Cv,
                   int M, int N, int K, int op, const int* __restrict__ start_pos)
{
    extern __shared__ __half hsm[];
    int tid = threadIdx.x, lane = tid & 31, warp = tid >> 5;
    int wm = warp & 1, wn = warp >> 1;
    int m0 = blockIdx.x * 128, n0 = blockIdx.y * 128;

    int crow = tid >> 1;
    int cc16 = (tid & 1) * 4;
    const __half* aSrc = A  + (size_t)(m0 + crow) * K + cc16 * 8;
    const __half* bSrc = Wt + (size_t)(n0 + crow) * K + cc16 * 8;
    uint32_t asBase = (uint32_t)__cvta_generic_to_shared(hsm);
    uint32_t bsBase = asBase + 3 * TILE_H * 2;
    uint32_t cOff = (uint32_t)(crow * 144 + cc16 * 16);

    float acc[4][4][4];
    #pragma unroll
    for (int i = 0; i < 4; i++)
        #pragma unroll
        for (int j = 0; j < 4; j++)
            #pragma unroll
            for (int r = 0; r < 4; r++) acc[i][j][r] = 0.f;

    int KT = K >> 6;

    #pragma unroll
    for (int s = 0; s < 2; s++) {
        int kk = s * 64;
        #pragma unroll
        for (int i = 0; i < 4; i++)
            cpasync16(asBase + s * (TILE_H * 2) + cOff + i * 16, aSrc + kk + i * 8);
        #pragma unroll
        for (int i = 0; i < 4; i++)
            cpasync16(bsBase + s * (TILE_H * 2) + cOff + i * 16, bSrc + kk + i * 8);
        asm volatile("cp.async.commit_group;");
    }

    uint32_t aLd = (uint32_t)((wm * 64 + (lane & 15)) * 144 + (lane >> 4) * 16);
    uint32_t bLd = (uint32_t)((wn * 32 + (lane & 15)) * 144 + (lane >> 4) * 16);

    for (int kt = 0; kt < KT; ++kt) {
        asm volatile("cp.async.wait_group 1;" ::: "memory");
        __syncthreads();

        uint32_t aSB = asBase + (kt % 3) * (TILE_H * 2);
        uint32_t bSB = bsBase + (kt % 3) * (TILE_H * 2);
        bool doPf = (kt + 2 < KT);
        int s2 = (kt + 2) % 3;
        int kk2 = (kt + 2) * 64;

        #pragma unroll
        for (int ks = 0; ks < 4; ++ks) {
            uint32_t afr[4][4], br[2][4];
            #pragma unroll
            for (int im = 0; im < 4; im++)
                ldsm4(aSB + aLd + im * 2304 + ks * 32,
                      afr[im][0], afr[im][1], afr[im][2], afr[im][3]);
            #pragma unroll
            for (int p = 0; p < 2; p++)
                ldsm4(bSB + bLd + p * 2304 + ks * 32,
                      br[p][0], br[p][1], br[p][2], br[p][3]);
            #pragma unroll
            for (int im = 0; im < 4; im++)
                #pragma unroll
                for (int in = 0; in < 4; in++) {
                    uint32_t bb[2] = { br[in >> 1][in & 1], br[in >> 1][(in & 1) + 2] };
                    mmah(acc[im][in], afr[im], bb);
                }

            // copy-issue reorder: interleave prefetch after first ks chunk
            if (ks == 0) {
                if (doPf) {
                    #pragma unroll
                    for (int i = 0; i < 4; i++)
                        cpasync16(asBase + s2 * (TILE_H * 2) + cOff + i * 16,
                                  aSrc + kk2 + i * 8);
                    #pragma unroll
                    for (int i = 0; i < 4; i++)
                        cpasync16(bsBase + s2 * (TILE_H * 2) + cOff + i * 16,
                                  bSrc + kk2 + i * 8);
                }
                asm volatile("cp.async.commit_group;");
            }
        }
    }

    int rbase = m0 + wm * 64 + (lane >> 2);
    int cbase = n0 + wn * 32 + ((lane & 3) << 1);
    #pragma unroll
    for (int im = 0; im < 4; im++) {
        #pragma unroll
        for (int hh = 0; hh < 2; hh++) {
            int row = rbase + im * 16 + hh * 8;
            bool zero = false;
            if (op == 2) zero = (row & 1023) < start_pos[row >> 10];
            #pragma unroll
            for (int in = 0; in < 4; in++) {
                int col = cbase + in * 8;
                float v0 = acc[im][in][hh * 2 + 0] + bias[col];
                float v1 = acc[im][in][hh * 2 + 1] + bias[col + 1];
                if (op == 1) {
                    v0 = 0.5f * v0 * (1.0f + erff(v0 * 0.70710678118654752f));
                    v1 = 0.5f * v1 * (1.0f + erff(v1 * 0.70710678118654752f));
                }
                if (op == 0 || op == 1) {
                    *(__half2*)((__half*)Cv + (size_t)row * N + col) =
                        __floats2half2_rn(v0, v1);
                } else {
                    if (zero) { v0 = 0.f; v1 = 0.f; }
                    float2 o; o.x = v0; o.y = v1;
                    *(float2*)((float*)Cv + (size_t)row * N + col) = o;
                }
            }
        }
    }
}

// ---------------- fp16 flash attention: 64-row Q tile, 4 warps --------------
#define AH 72

__global__ __launch_bounds__(128)
void attn_h_kernel(const __half* __restrict__ QKV, __half* __restrict__ O,
                   const int* __restrict__ start_pos)
{
    __shared__ __half sQ[64 * AH], sK[64 * AH], sVt[64 * AH], sP[64 * AH];
    uint32_t* pW = (uint32_t*)sP;

    int tid = threadIdx.x, lane = tid & 31, warp = tid >> 5;
    int qt = blockIdx.x, bh = blockIdx.y;
    int b = bh >> 4, h = bh & 15;
    int sp = start_pos[b];
    float slope = exp2f(-0.5f * (float)(h + 1));
    int brow = b * Sz;

    const __half* Qg = QKV + h * 64;
    const __half* Kg = QKV + 1024 + h * 64;
    const __half* Vg = QKV + 2048 + h * 64;

    uint32_t sQb = (uint32_t)__cvta_generic_to_shared(sQ);
    uint32_t sKb = (uint32_t)__cvta_generic_to_shared(sK);
    uint32_t sVb = (uint32_t)__cvta_generic_to_shared(sVt);
    uint32_t sPb = (uint32_t)__cvta_generic_to_shared(sP);

    const __half2 hscale = __float2half2_rn(0.125f);
    for (int i = tid; i < 64 * 16; i += 128) {
        int row = i >> 4, d4 = (i & 15) * 4;
        uint2 u = *(const uint2*)(Qg + (size_t)(brow + qt * 64 + row) * QKVN + d4);
        __half2 h0 = __hmul2(*(__half2*)&u.x, hscale);
        __half2 h1 = __hmul2(*(__half2*)&u.y, hscale);
        uint2 o; o.x = *(uint32_t*)&h0; o.y = *(uint32_t*)&h1;
        *(uint2*)(sQ + row * AH + d4) = o;
    }

    int qrow = warp * 16 + (lane >> 2);
    int cA   = lane & 3;
    int ig0 = qt * 64 + qrow, ig1 = ig0 + 8;

    uint32_t fragQ = (uint32_t)((warp * 16 + (lane & 15)) * 144 + (lane >> 4) * 16);
    uint32_t fragB = (uint32_t)((lane & 15) * 144 + (lane >> 4) * 16);

    float m0 = -1e30f, m1 = -1e30f, l0 = 0.f, l1 = 0.f;
    float oacc[8][4];
    #pragma unroll
    for (int n = 0; n < 8; n++)
        #pragma unroll
        for (int r = 0; r < 4; r++) oacc[n][r] = 0.f;

    int ktmax = (qt * 64 >= sp) ? qt : 15;

    for (int kt = 0; kt <= ktmax; ++kt) {
        __syncthreads();
        for (int i = tid; i < 64 * 16; i += 128) {
            int row = i >> 4, d4 = (i & 15) * 4;
            uint2 uk = *(const uint2*)(Kg + (size_t)(brow + kt * 64 + row) * QKVN + d4);
            *(uint2*)(sK + row * AH + d4) = uk;
            uint2 uv = *(const uint2*)(Vg + (size_t)(brow + kt * 64 + row) * QKVN + d4);
            __half vh[4];
            *(uint2*)vh = uv;
            #pragma unroll
            for (int j = 0; j < 4; j++)
                sVt[(d4 + j) * AH + row] = vh[j];
        }
        __syncthreads();

        float sacc[8][4];
        #pragma unroll
        for (int n = 0; n < 8; n++)
            #pragma unroll
            for (int r = 0; r < 4; r++) sacc[n][r] = 0.f;

        #pragma unroll
        for (int ks = 0; ks < 4; ++ks) {
            uint32_t af[4], br[4][4];
            ldsm4(sQb + fragQ + ks * 32, af[0], af[1], af[2], af[3]);
            #pragma unroll
            for (int p = 0; p < 4; p++)
                ldsm4(sKb + fragB + p * 2304 + ks * 32,
                      br[p][0], br[p][1], br[p][2], br[p][3]);
            #pragma unroll
            for (int n = 0; n < 8; n++) {
                uint32_t bb[2] = { br[n >> 1][n & 1], br[n >> 1][(n & 1) + 2] };
                mmah(sacc[n], af, bb);
            }
        }

        #pragma unroll
        for (int n = 0; n < 8; n++) {
            int jg = kt * 64 + n * 8 + cA * 2;
            #pragma unroll
            for (int half = 0; half < 2; half++) {
                int j = jg + half;
                float al = slope * (float)(j - sp);
                bool ok0 = (j <= ig0) || (ig0 < sp) || (j < sp);
                bool ok1 = (j <= ig1) || (ig1 < sp) || (j < sp);
                sacc[n][half]     = ok0 ? sacc[n][half]     + al : -1e30f;
                sacc[n][half + 2] = ok1 ? sacc[n][half + 2] + al : -1e30f;
            }
        }

        float t0 = -1e30f, t1 = -1e30f;
        #pragma unroll
        for (int n = 0; n < 8; n++) {
            t0 = fmaxf(t0, fmaxf(sacc[n][0], sacc[n][1]));
            t1 = fmaxf(t1, fmaxf(sacc[n][2], sacc[n][3]));
        }
        t0 = fmaxf(t0, __shfl_xor_sync(0xffffffffu, t0, 1));
        t0 = fmaxf(t0, __shfl_xor_sync(0xffffffffu, t0, 2));
        t1 = fmaxf(t1, __shfl_xor_sync(0xffffffffu, t1, 1));
        t1 = fmaxf(t1, __shfl_xor_sync(0xffffffffu, t1, 2));

        float mn0 = fmaxf(m0, t0), mn1 = fmaxf(m1, t1);
        float scl0 = __expf(m0 - mn0), scl1 = __expf(m1 - mn1);
        m0 = mn0; m1 = mn1;

        float ls0 = 0.f, ls1 = 0.f;
        #pragma unroll
        for (int n = 0; n < 8; n++) {
            __half2 hp0 = __floats2half2_rn(__expf(sacc[n][0] - mn0),
                                            __expf(sacc[n][1] - mn0));
            __half2 hp1 = __floats2half2_rn(__expf(sacc[n][2] - mn1),
                                            __expf(sacc[n][3] - mn1));
            float2 f0 = __half22float2(hp0);
            float2 f1 = __half22float2(hp1);
            ls0 += f0.x + f0.y;
            ls1 += f1.x + f1.y;
            pW[(qrow)     * 36 + n * 4 + cA] = *(uint32_t*)&hp0;
            pW[(qrow + 8) * 36 + n * 4 + cA] = *(uint32_t*)&hp1;
        }
        ls0 += __shfl_xor_sync(0xffffffffu, ls0, 1);
        ls0 += __shfl_xor_sync(0xffffffffu, ls0, 2);
        ls1 += __shfl_xor_sync(0xffffffffu, ls1, 1);
        ls1 += __shfl_xor_sync(0xffffffffu, ls1, 2);
        l0 = l0 * scl0 + ls0;
        l1 = l1 * scl1 + ls1;

        #pragma unroll
        for (int n = 0; n < 8; n++) {
            oacc[n][0] *= scl0; oacc[n][1] *= scl0;
            oacc[n][2] *= scl1; oacc[n][3] *= scl1;
        }
        __syncwarp();

        #pragma unroll
        for (int ks = 0; ks < 4; ++ks) {
            uint32_t af[4], br[4][4];
            ldsm4(sPb + fragQ + ks * 32, af[0], af[1], af[2], af[3]);
            #pragma unroll
            for (int p = 0; p < 4; p++)
                ldsm4(sVb + fragB + p * 2304 + ks * 32,
                      br[p][0], br[p][1], br[p][2], br[p][3]);
            #pragma unroll
            for (int n = 0; n < 8; n++) {
                uint32_t bb[2] = { br[n >> 1][n & 1], br[n >> 1][(n & 1) + 2] };
                mmah(oacc[n], af, bb);
            }
        }
        __syncwarp();
    }

    float inv0 = 1.f / l0, inv1 = 1.f / l1;
    size_t orow0 = (size_t)(brow + qt * 64 + qrow) * Hz + h * 64;
    size_t orow1 = orow0 + (size_t)8 * Hz;
    #pragma unroll
    for (int n = 0; n < 8; n++) {
        int col = n * 8 + cA * 2;
        *(__half2*)(O + orow0 + col) = __floats2half2_rn(oacc[n][0] * inv0, oacc[n][1] * inv0);
        *(__half2*)(O + orow1 + col) = __floats2half2_rn(oacc[n][2] * inv1, oacc[n][3] * inv1);
    }
}

// ------------------------ fused residual + layernorm -----------------------
__inline__ __device__ float warp_sum(float v) {
    #pragma unroll
    for (int o = 16; o; o >>= 1) v += __shfl_xor_sync(0xffffffffu, v, o);
    return v;
}

__global__ void add_ln_kernel(float* __restrict__ x, __half* __restrict__ xch,
                              const float* __restrict__ t,
                              const float* __restrict__ g, const float* __restrict__ b)
{
    int row = blockIdx.x;
    int tid = threadIdx.x;
    size_t off = (size_t)row * Hz + tid * 4;

    float4 xv = *(const float4*)(x + off);
    float4 tv = *(const float4*)(t + off);
    float v0 = xv.x + tv.x, v1 = xv.y + tv.y, v2 = xv.z + tv.z, v3 = xv.w + tv.w;

    float s  = v0 + v1 + v2 + v3;
    float s2 = v0 * v0 + v1 * v1 + v2 * v2 + v3 * v3;

    __shared__ float sh1[8], sh2[8];
    int lane = tid & 31, wid = tid >> 5;
    s  = warp_sum(s);
    s2 = warp_sum(s2);
    if (lane == 0) { sh1[wid] = s; sh2[wid] = s2; }
    __syncthreads();
    if (wid == 0) {
        float a = (lane < 8) ? sh1[lane] : 0.f;
        float c = (lane < 8) ? sh2[lane] : 0.f;
        a = warp_sum(a);
        c = warp_sum(c);
        if (lane == 0) { sh1[0] = a; sh2[0] = c; }
    }
    __syncthreads();

    float mu  = sh1[0] * (1.0f / Hz);
    float var = sh2[0] * (1.0f / Hz) - mu * mu;
    float inv = rsqrtf(var + 1e-5f);

    int cbase = tid * 4;
    float4 gv = *(const float4*)(g + cbase);
    float4 bv = *(const float4*)(b + cbase);
    float4 out;
    out.x = (v0 - mu) * inv * gv.x + bv.x;
    out.y = (v1 - mu) * inv * gv.y + bv.y;
    out.z = (v2 - mu) * inv * gv.z + bv.z;
    out.w = (v3 - mu) * inv * gv.w + bv.w;
    *(float4*)(x + off) = out;
    *(__half2*)(xch + off)     = __floats2half2_rn(out.x, out.y);
    *(__half2*)(xch + off + 2) = __floats2half2_rn(out.z, out.w);
}

// --------------------------------- launch ----------------------------------
extern "C" void kernel_launch(void* const* d_in, const int* in_sizes, int n_in,
                              void* d_out, int out_size)
{
    const int*   ids  = (const int*)d_in[0];
    const int*   sp   = (const int*)d_in[1];
    const float* emb  = (const float*)d_in[2];
    const float* Wq   = (const float*)d_in[3];
    const float* bq   = (const float*)d_in[4];
    const float* Wk   = (const float*)d_in[5];
    const float* bk   = (const float*)d_in[6];
    const float* Wv   = (const float*)d_in[7];
    const float* bv   = (const float*)d_in[8];
    const float* Wo   = (const float*)d_in[9];
    const float* bo   = (const float*)d_in[10];
    const float* ln1g = (const float*)d_in[11];
    const float* ln1b = (const float*)d_in[12];
    const float* ln2g = (const float*)d_in[13];
    const float* ln2b = (const float*)d_in[14];
    const float* W1   = (const float*)d_in[15];
    const float* b1   = (const float*)d_in[16];
    const float* W2   = (const float*)d_in[17];
    const float* b2   = (const float*)d_in[18];
    const float* Wf   = (const float*)d_in[19];
    const float* bf   = (const float*)d_in[20];
    float* out = (float*)d_out;

    float *x, *tmp, *bqkv;
    __half *xch, *qkv, *attnc, *ffc, *w;
    cudaGetSymbolAddress((void**)&x,     g_x);
    cudaGetSymbolAddress((void**)&xch,   g_xch);
    cudaGetSymbolAddress((void**)&qkv,   g_qkv);
    cudaGetSymbolAddress((void**)&attnc, g_attnc);
    cudaGetSymbolAddress((void**)&tmp,   g_tmp);
    cudaGetSymbolAddress((void**)&ffc,   g_ffc);
    cudaGetSymbolAddress((void**)&w,     g_w);
    cudaGetSymbolAddress((void**)&bqkv,  g_bqkv);

    cudaFuncSetAttribute(gemm_h_kernel, cudaFuncAttributeMaxDynamicSharedMemorySize, GEMM_SMEM);

    prep_all_kernel<<<PREP_TILES, dim3(32, 8)>>>(Wq, Wk, Wv, Wo, W1, W2, Wf, w);
    cvt_bias_kernel<<<(Lz * QKVN) / 256, 256>>>(bq, bk, bv, bqkv);
    embed_kernel<<<Mz, 256>>>(ids, emb, x, xch);

    for (int l = 0; l < Lz; ++l) {
        gemm_h_kernel<<<dim3(Mz / 128, QKVN / 128), 256, GEMM_SMEM>>>(
            xch, w + OFF_QKV + (size_t)l * Hz * QKVN, bqkv + l * QKVN, qkv,
            Mz, QKVN, Hz, 0, sp);

        attn_h_kernel<<<dim3(Sz / 64, Bz * NHz), 128>>>(qkv, attnc, sp);

        gemm_h_kernel<<<dim3(Mz / 128, Hz / 128), 256, GEMM_SMEM>>>(
            attnc, w + OFF_WO + (size_t)l * Hz * Hz, bo + l * Hz, tmp,
            Mz, Hz, Hz, 3, sp);
        add_ln_kernel<<<Mz, 256>>>(x, xch, tmp, ln1g + l * Hz, ln1b + l * Hz);

        gemm_h_kernel<<<dim3(Mz / 128, DFz / 128), 256, GEMM_SMEM>>>(
            xch, w + OFF_W1 + (size_t)l * Hz * DFz, b1 + l * DFz, ffc,
            Mz, DFz, Hz, 1, sp);
        gemm_h_kernel<<<dim3(Mz / 128, Hz / 128), 256, GEMM_SMEM>>>(
            ffc, w + OFF_W2 + (size_t)l * DFz * Hz, b2 + l * Hz, tmp,
            Mz, Hz, DFz, 3, sp);
        add_ln_kernel<<<Mz, 256>>>(x, xch, tmp, ln2g + l * Hz, ln2b + l * Hz);
    }

    gemm_h_kernel<<<dim3(Mz / 128, Vz / 128), 256, GEMM_SMEM>>>(
        xch, w + OFF_WF, bf, out, Mz, Vz, Hz, 2, sp);
}

// round 12
// speedup vs baseline: 1.1544x; 1.0989x over previous
#include <cuda_runtime.h>
#include <cuda_fp16.h>
#include <math.h>
#include <stdint.h>

// ---------------------------------------------------------------------------
// TidalTransformer: B=4, S=1024, H=1024, NH=16, DK=64, DF=4096, L=4, V=32000
// Round 12: GEMM issue-slot diet (direct-operand mma, LDSM/MMA interleave,
//           spread prefetch) + R11 attention/prep/LN.
// ---------------------------------------------------------------------------

#define Bz   4
#define Sz   1024
#define Hz   1024
#define NHz  16
#define DKz  64
#define DFz  4096
#define Lz   4
#define Vz   32000
#define Mz   (Bz * Sz)
#define QKVN 3072

// ------------------------- scratch (device globals) ------------------------
__device__ float  g_x   [(size_t)Mz * Hz];
__device__ __half g_xch [(size_t)Mz * Hz];
__device__ __half g_qkv [(size_t)Mz * QKVN];
__device__ __half g_attnc[(size_t)Mz * Hz];
__device__ float  g_tmp [(size_t)Mz * Hz];
__device__ __half g_ffc [(size_t)Mz * DFz];

#define OFF_QKV 0
#define OFF_WO  ((size_t)12582912)
#define OFF_W1  ((size_t)16777216)
#define OFF_W2  ((size_t)33554432)
#define OFF_WF  ((size_t)50331648)
__device__ __half g_w[(size_t)83099648];
__device__ float  g_bqkv[Lz * QKVN];

// ----------------------- merged weight prep --------------------------------
#define PREP_TILES 81152

__global__ void prep_all_kernel(const float* __restrict__ Wq, const float* __restrict__ Wk,
                                const float* __restrict__ Wv, const float* __restrict__ Wo,
                                const float* __restrict__ W1, const float* __restrict__ W2,
                                const float* __restrict__ Wf, __half* __restrict__ w)
{
    __shared__ float t[32][33];
    int idx = blockIdx.x;
    const float* src;
    __half* dst;
    int K, N;

    if (idx < 4096) {
        int l = idx >> 10; idx &= 1023;
        src = Wq + (size_t)l * Hz * Hz; dst = w + OFF_QKV + (size_t)l * Hz * QKVN;
        K = Hz; N = Hz;
    } else if (idx < 8192) {
        idx -= 4096; int l = idx >> 10; idx &= 1023;
        src = Wk + (size_t)l * Hz * Hz;
        dst = w + OFF_QKV + (size_t)l * Hz * QKVN + (size_t)1024 * Hz;
        K = Hz; N = Hz;
    } else if (idx < 12288) {
        idx -= 8192; int l = idx >> 10; idx &= 1023;
        src = Wv + (size_t)l * Hz * Hz;
        dst = w + OFF_QKV + (size_t)l * Hz * QKVN + (size_t)2048 * Hz;
        K = Hz; N = Hz;
    } else if (idx < 16384) {
        idx -= 12288; int l = idx >> 10; idx &= 1023;
        src = Wo + (size_t)l * Hz * Hz; dst = w + OFF_WO + (size_t)l * Hz * Hz;
        K = Hz; N = Hz;
    } else if (idx < 32768) {
        idx -= 16384; int l = idx >> 12; idx &= 4095;
        src = W1 + (size_t)l * Hz * DFz; dst = w + OFF_W1 + (size_t)l * Hz * DFz;
        K = Hz; N = DFz;
    } else if (idx < 49152) {
        idx -= 32768; int l = idx >> 12; idx &= 4095;
        src = W2 + (size_t)l * DFz * Hz; dst = w + OFF_W2 + (size_t)l * DFz * Hz;
        K = DFz; N = Hz;
    } else {
        idx -= 49152;
        src = Wf; dst = w + OFF_WF;
        K = Hz; N = Vz;
    }

    int nt = N >> 5;
    int kb = (idx / nt) * 32, nb = (idx % nt) * 32;
    int tx = threadIdx.x, ty = threadIdx.y;
    #pragma unroll
    for (int i = 0; i < 4; i++)
        t[ty + i * 8][tx] = src[(size_t)(kb + ty + i * 8) * N + nb + tx];
    __syncthreads();
    #pragma unroll
    for (int i = 0; i < 4; i++)
        dst[(size_t)(nb + ty + i * 8) * K + kb + tx] = __float2half_rn(t[tx][ty + i * 8]);
}

__global__ void cvt_bias_kernel(const float* __restrict__ bq, const float* __restrict__ bk,
                                const float* __restrict__ bv, float* __restrict__ dst)
{
    int i = blockIdx.x * 256 + threadIdx.x;
    int n = i % QKVN, l = i / QKVN;
    float v;
    if (n < 1024)       v = bq[l * 1024 + n];
    else if (n < 2048)  v = bk[l * 1024 + n - 1024];
    else                v = bv[l * 1024 + n - 2048];
    dst[i] = v;
}

// ------------------------------- embedding ---------------------------------
__global__ void embed_kernel(const int* __restrict__ ids,
                             const float* __restrict__ emb,
                             float* __restrict__ x, __half* __restrict__ xch)
{
    int row = blockIdx.x;
    int tid = threadIdx.x;
    int id  = ids[row];
    float4 v = *(const float4*)(emb + (size_t)id * Hz + tid * 4);
    v.x *= 32.0f; v.y *= 32.0f; v.z *= 32.0f; v.w *= 32.0f;
    *(float4*)(x + (size_t)row * Hz + tid * 4) = v;
    *(__half2*)(xch + (size_t)row * Hz + tid * 4)     = __floats2half2_rn(v.x, v.y);
    *(__half2*)(xch + (size_t)row * Hz + tid * 4 + 2) = __floats2half2_rn(v.z, v.w);
}

// ---------------------------- mma / ldmatrix -------------------------------
__device__ __forceinline__ void mmah2(float* c, const uint32_t* a,
                                      uint32_t b0, uint32_t b1) {
    asm volatile(
        "mma.sync.aligned.m16n8k16.row.col.f32.f16.f16.f32 "
        "{%0,%1,%2,%3},{%4,%5,%6,%7},{%8,%9},{%0,%1,%2,%3};"
        : "+f"(c[0]), "+f"(c[1]), "+f"(c[2]), "+f"(c[3])
        : "r"(a[0]), "r"(a[1]), "r"(a[2]), "r"(a[3]), "r"(b0), "r"(b1));
}
__device__ __forceinline__ void ldsm4(uint32_t addr, uint32_t& r0, uint32_t& r1,
                                      uint32_t& r2, uint32_t& r3) {
    asm volatile("ldmatrix.sync.aligned.m8n8.x4.shared.b16 {%0,%1,%2,%3}, [%4];"
                 : "=r"(r0), "=r"(r1), "=r"(r2), "=r"(r3) : "r"(addr));
}
__device__ __forceinline__ void cpasync16(uint32_t dst, const void* src) {
    asm volatile("cp.async.cg.shared.global [%0], [%1], 16;" :: "r"(dst), "l"(src));
}

// ------------------ fp16 GEMM: 128x128 tile, BK=64, 3-stage ----------------
#define HSTR 72
#define TILE_H (128 * HSTR)
#define GEMM_SMEM (6 * TILE_H * 2)

__global__ __launch_bounds__(256, 2)
void gemm_h_kernel(const __half* __restrict__ A, const __half* __restrict__ Wt,
                   const float* __restrict__ bias, void* __restrict__ Cv,
                   int M, int N, int K, int op, const int* __restrict__ start_pos)
{
    extern __shared__ __half hsm[];
    int tid = threadIdx.x, lane = tid & 31, warp = tid >> 5;
    int wm = warp & 1, wn = warp >> 1;
    int m0 = blockIdx.x * 128, n0 = blockIdx.y * 128;

    int crow = tid >> 1;
    int cc16 = (tid & 1) * 4;
    const __half* aSrc = A  + (size_t)(m0 + crow) * K + cc16 * 8;
    const __half* bSrc = Wt + (size_t)(n0 + crow) * K + cc16 * 8;
    uint32_t asBase = (uint32_t)__cvta_generic_to_shared(hsm);
    uint32_t bsBase = asBase + 3 * TILE_H * 2;
    uint32_t cOff = (uint32_t)(crow * 144 + cc16 * 16);

    float acc[4][4][4];
    #pragma unroll
    for (int i = 0; i < 4; i++)
        #pragma unroll
        for (int j = 0; j < 4; j++)
            #pragma unroll
            for (int r = 0; r < 4; r++) acc[i][j][r] = 0.f;

    int KT = K >> 6;

    #pragma unroll
    for (int s = 0; s < 2; s++) {
        int kk = s * 64;
        #pragma unroll
        for (int i = 0; i < 4; i++)
            cpasync16(asBase + s * (TILE_H * 2) + cOff + i * 16, aSrc + kk + i * 8);
        #pragma unroll
        for (int i = 0; i < 4; i++)
            cpasync16(bsBase + s * (TILE_H * 2) + cOff + i * 16, bSrc + kk + i * 8);
        asm volatile("cp.async.commit_group;");
    }

    uint32_t aLd = (uint32_t)((wm * 64 + (lane & 15)) * 144 + (lane >> 4) * 16);
    uint32_t bLd = (uint32_t)((wn * 32 + (lane & 15)) * 144 + (lane >> 4) * 16);

    for (int kt = 0; kt < KT; ++kt) {
        asm volatile("cp.async.wait_group 1;" ::: "memory");
        __syncthreads();

        uint32_t aSB = asBase + (kt % 3) * (TILE_H * 2);
        uint32_t bSB = bsBase + (kt % 3) * (TILE_H * 2);
        bool doPf = (kt + 2 < KT);
        int s2 = (kt + 2) % 3;
        int kk2 = (kt + 2) * 64;

        #pragma unroll
        for (int ks = 0; ks < 4; ++ks) {
            uint32_t br[2][4];
            #pragma unroll
            for (int p = 0; p < 2; p++)
                ldsm4(bSB + bLd + p * 2304 + ks * 32,
                      br[p][0], br[p][1], br[p][2], br[p][3]);

            uint32_t aCur[4], aNext[4];
            ldsm4(aSB + aLd + ks * 32, aCur[0], aCur[1], aCur[2], aCur[3]);

            #pragma unroll
            for (int im = 0; im < 4; im++) {
                if (im < 3)
                    ldsm4(aSB + aLd + (im + 1) * 2304 + ks * 32,
                          aNext[0], aNext[1], aNext[2], aNext[3]);
                mmah2(acc[im][0], aCur, br[0][0], br[0][2]);
                mmah2(acc[im][1], aCur, br[0][1], br[0][3]);
                mmah2(acc[im][2], aCur, br[1][0], br[1][2]);
                mmah2(acc[im][3], aCur, br[1][1], br[1][3]);
                #pragma unroll
                for (int r = 0; r < 4; r++) aCur[r] = aNext[r];
            }

            // spread prefetch: A chunks at ks=0, B chunks + commit at ks=1
            if (ks == 0 && doPf) {
                #pragma unroll
                for (int i = 0; i < 4; i++)
                    cpasync16(asBase + s2 * (TILE_H * 2) + cOff + i * 16,
                              aSrc + kk2 + i * 8);
            }
            if (ks == 1) {
                if (doPf) {
                    #pragma unroll
                    for (int i = 0; i < 4; i++)
                        cpasync16(bsBase + s2 * (TILE_H * 2) + cOff + i * 16,
                                  bSrc + kk2 + i * 8);
                }
                asm volatile("cp.async.commit_group;");
            }
        }
    }

    int rbase = m0 + wm * 64 + (lane >> 2);
    int cbase = n0 + wn * 32 + ((lane & 3) << 1);
    #pragma unroll
    for (int im = 0; im < 4; im++) {
        #pragma unroll
        for (int hh = 0; hh < 2; hh++) {
            int row = rbase + im * 16 + hh * 8;
            bool zero = false;
            if (op == 2) zero = (row & 1023) < start_pos[row >> 10];
            #pragma unroll
            for (int in = 0; in < 4; in++) {
                int col = cbase + in * 8;
                float v0 = acc[im][in][hh * 2 + 0] + bias[col];
                float v1 = acc[im][in][hh * 2 + 1] + bias[col + 1];
                if (op == 1) {
                    v0 = 0.5f * v0 * (1.0f + erff(v0 * 0.70710678118654752f));
                    v1 = 0.5f * v1 * (1.0f + erff(v1 * 0.70710678118654752f));
                }
                if (op == 0 || op == 1) {
                    *(__half2*)((__half*)Cv + (size_t)row * N + col) =
                        __floats2half2_rn(v0, v1);
                } else {
                    if (zero) { v0 = 0.f; v1 = 0.f; }
                    float2 o; o.x = v0; o.y = v1;
                    *(float2*)((float*)Cv + (size_t)row * N + col) = o;
                }
            }
        }
    }
}

// ---------------- fp16 flash attention: 64-row Q tile, 4 warps --------------
#define AH 72

__global__ __launch_bounds__(128)
void attn_h_kernel(const __half* __restrict__ QKV, __half* __restrict__ O,
                   const int* __restrict__ start_pos)
{
    __shared__ __half sQ[64 * AH], sK[64 * AH], sVt[64 * AH], sP[64 * AH];
    uint32_t* pW = (uint32_t*)sP;

    int tid = threadIdx.x, lane = tid & 31, warp = tid >> 5;
    int qt = blockIdx.x, bh = blockIdx.y;
    int b = bh >> 4, h = bh & 15;
    int sp = start_pos[b];
    float slope = exp2f(-0.5f * (float)(h + 1));
    int brow = b * Sz;

    const __half* Qg = QKV + h * 64;
    const __half* Kg = QKV + 1024 + h * 64;
    const __half* Vg = QKV + 2048 + h * 64;

    uint32_t sQb = (uint32_t)__cvta_generic_to_shared(sQ);
    uint32_t sKb = (uint32_t)__cvta_generic_to_shared(sK);
    uint32_t sVb = (uint32_t)__cvta_generic_to_shared(sVt);
    uint32_t sPb = (uint32_t)__cvta_generic_to_shared(sP);

    const __half2 hscale = __float2half2_rn(0.125f);
    for (int i = tid; i < 64 * 16; i += 128) {
        int row = i >> 4, d4 = (i & 15) * 4;
        uint2 u = *(const uint2*)(Qg + (size_t)(brow + qt * 64 + row) * QKVN + d4);
        __half2 h0 = __hmul2(*(__half2*)&u.x, hscale);
        __half2 h1 = __hmul2(*(__half2*)&u.y, hscale);
        uint2 o; o.x = *(uint32_t*)&h0; o.y = *(uint32_t*)&h1;
        *(uint2*)(sQ + row * AH + d4) = o;
    }

    int qrow = warp * 16 + (lane >> 2);
    int cA   = lane & 3;
    int ig0 = qt * 64 + qrow, ig1 = ig0 + 8;

    uint32_t fragQ = (uint32_t)((warp * 16 + (lane & 15)) * 144 + (lane >> 4) * 16);
    uint32_t fragB = (uint32_t)((lane & 15) * 144 + (lane >> 4) * 16);

    float m0 = -1e30f, m1 = -1e30f, l0 = 0.f, l1 = 0.f;
    float oacc[8][4];
    #pragma unroll
    for (int n = 0; n < 8; n++)
        #pragma unroll
        for (int r = 0; r < 4; r++) oacc[n][r] = 0.f;

    int ktmax = (qt * 64 >= sp) ? qt : 15;

    for (int kt = 0; kt <= ktmax; ++kt) {
        __syncthreads();
        for (int i = tid; i < 64 * 16; i += 128) {
            int row = i >> 4, d4 = (i & 15) * 4;
            uint2 uk = *(const uint2*)(Kg + (size_t)(brow + kt * 64 + row) * QKVN + d4);
            *(uint2*)(sK + row * AH + d4) = uk;
            uint2 uv = *(const uint2*)(Vg + (size_t)(brow + kt * 64 + row) * QKVN + d4);
            __half vh[4];
            *(uint2*)vh = uv;
            #pragma unroll
            for (int j = 0; j < 4; j++)
                sVt[(d4 + j) * AH + row] = vh[j];
        }
        __syncthreads();

        float sacc[8][4];
        #pragma unroll
        for (int n = 0; n < 8; n++)
            #pragma unroll
            for (int r = 0; r < 4; r++) sacc[n][r] = 0.f;

        #pragma unroll
        for (int ks = 0; ks < 4; ++ks) {
            uint32_t af[4], br[4][4];
            ldsm4(sQb + fragQ + ks * 32, af[0], af[1], af[2], af[3]);
            #pragma unroll
            for (int p = 0; p < 4; p++)
                ldsm4(sKb + fragB + p * 2304 + ks * 32,
                      br[p][0], br[p][1], br[p][2], br[p][3]);
            #pragma unroll
            for (int n = 0; n < 8; n++)
                mmah2(sacc[n], af, br[n >> 1][n & 1], br[n >> 1][(n & 1) + 2]);
        }

        #pragma unroll
        for (int n = 0; n < 8; n++) {
            int jg = kt * 64 + n * 8 + cA * 2;
            #pragma unroll
            for (int half = 0; half < 2; half++) {
                int j = jg + half;
                float al = slope * (float)(j - sp);
                bool ok0 = (j <= ig0) || (ig0 < sp) || (j < sp);
                bool ok1 = (j <= ig1) || (ig1 < sp) || (j < sp);
                sacc[n][half]     = ok0 ? sacc[n][half]     + al : -1e30f;
                sacc[n][half + 2] = ok1 ? sacc[n][half + 2] + al : -1e30f;
            }
        }

        float t0 = -1e30f, t1 = -1e30f;
        #pragma unroll
        for (int n = 0; n < 8; n++) {
            t0 = fmaxf(t0, fmaxf(sacc[n][0], sacc[n][1]));
            t1 = fmaxf(t1, fmaxf(sacc[n][2], sacc[n][3]));
        }
        t0 = fmaxf(t0, __shfl_xor_sync(0xffffffffu, t0, 1));
        t0 = fmaxf(t0, __shfl_xor_sync(0xffffffffu, t0, 2));
        t1 = fmaxf(t1, __shfl_xor_sync(0xffffffffu, t1, 1));
        t1 = fmaxf(t1, __shfl_xor_sync(0xffffffffu, t1, 2));

        float mn0 = fmaxf(m0, t0), mn1 = fmaxf(m1, t1);
        float scl0 = __expf(m0 - mn0), scl1 = __expf(m1 - mn1);
        m0 = mn0; m1 = mn1;

        float ls0 = 0.f, ls1 = 0.f;
        #pragma unroll
        for (int n = 0; n < 8; n++) {
            __half2 hp0 = __floats2half2_rn(__expf(sacc[n][0] - mn0),
                                            __expf(sacc[n][1] - mn0));
            __half2 hp1 = __floats2half2_rn(__expf(sacc[n][2] - mn1),
                                            __expf(sacc[n][3] - mn1));
            float2 f0 = __half22float2(hp0);
            float2 f1 = __half22float2(hp1);
            ls0 += f0.x + f0.y;
            ls1 += f1.x + f1.y;
            pW[(qrow)     * 36 + n * 4 + cA] = *(uint32_t*)&hp0;
            pW[(qrow + 8) * 36 + n * 4 + cA] = *(uint32_t*)&hp1;
        }
        ls0 += __shfl_xor_sync(0xffffffffu, ls0, 1);
        ls0 += __shfl_xor_sync(0xffffffffu, ls0, 2);
        ls1 += __shfl_xor_sync(0xffffffffu, ls1, 1);
        ls1 += __shfl_xor_sync(0xffffffffu, ls1, 2);
        l0 = l0 * scl0 + ls0;
        l1 = l1 * scl1 + ls1;

        #pragma unroll
        for (int n = 0; n < 8; n++) {
            oacc[n][0] *= scl0; oacc[n][1] *= scl0;
            oacc[n][2] *= scl1; oacc[n][3] *= scl1;
        }
        __syncwarp();

        #pragma unroll
        for (int ks = 0; ks < 4; ++ks) {
            uint32_t af[4], br[4][4];
            ldsm4(sPb + fragQ + ks * 32, af[0], af[1], af[2], af[3]);
            #pragma unroll
            for (int p = 0; p < 4; p++)
                ldsm4(sVb + fragB + p * 2304 + ks * 32,
                      br[p][0], br[p][1], br[p][2], br[p][3]);
            #pragma unroll
            for (int n = 0; n < 8; n++)
                mmah2(oacc[n], af, br[n >> 1][n & 1], br[n >> 1][(n & 1) + 2]);
        }
        __syncwarp();
    }

    float inv0 = 1.f / l0, inv1 = 1.f / l1;
    size_t orow0 = (size_t)(brow + qt * 64 + qrow) * Hz + h * 64;
    size_t orow1 = orow0 + (size_t)8 * Hz;
    #pragma unroll
    for (int n = 0; n < 8; n++) {
        int col = n * 8 + cA * 2;
        *(__half2*)(O + orow0 + col) = __floats2half2_rn(oacc[n][0] * inv0, oacc[n][1] * inv0);
        *(__half2*)(O + orow1 + col) = __floats2half2_rn(oacc[n][2] * inv1, oacc[n][3] * inv1);
    }
}

// ------------------------ fused residual + layernorm -----------------------
__inline__ __device__ float warp_sum(float v) {
    #pragma unroll
    for (int o = 16; o; o >>= 1) v += __shfl_xor_sync(0xffffffffu, v, o);
    return v;
}

__global__ void add_ln_kernel(float* __restrict__ x, __half* __restrict__ xch,
                              const float* __restrict__ t,
                              const float* __restrict__ g, const float* __restrict__ b)
{
    int row = blockIdx.x;
    int tid = threadIdx.x;
    size_t off = (size_t)row * Hz + tid * 4;

    float4 xv = *(const float4*)(x + off);
    float4 tv = *(const float4*)(t + off);
    float v0 = xv.x + tv.x, v1 = xv.y + tv.y, v2 = xv.z + tv.z, v3 = xv.w + tv.w;

    float s  = v0 + v1 + v2 + v3;
    float s2 = v0 * v0 + v1 * v1 + v2 * v2 + v3 * v3;

    __shared__ float sh1[8], sh2[8];
    int lane = tid & 31, wid = tid >> 5;
    s  = warp_sum(s);
    s2 = warp_sum(s2);
    if (lane == 0) { sh1[wid] = s; sh2[wid] = s2; }
    __syncthreads();
    if (wid == 0) {
        float a = (lane < 8) ? sh1[lane] : 0.f;
        float c = (lane < 8) ? sh2[lane] : 0.f;
        a = warp_sum(a);
        c = warp_sum(c);
        if (lane == 0) { sh1[0] = a; sh2[0] = c; }
    }
    __syncthreads();

    float mu  = sh1[0] * (1.0f / Hz);
    float var = sh2[0] * (1.0f / Hz) - mu * mu;
    float inv = rsqrtf(var + 1e-5f);

    int cbase = tid * 4;
    float4 gv = *(const float4*)(g + cbase);
    float4 bv = *(const float4*)(b + cbase);
    float4 out;
    out.x = (v0 - mu) * inv * gv.x + bv.x;
    out.y = (v1 - mu) * inv * gv.y + bv.y;
    out.z = (v2 - mu) * inv * gv.z + bv.z;
    out.w = (v3 - mu) * inv * gv.w + bv.w;
    *(float4*)(x + off) = out;
    *(__half2*)(xch + off)     = __floats2half2_rn(out.x, out.y);
    *(__half2*)(xch + off + 2) = __floats2half2_rn(out.z, out.w);
}

// --------------------------------- launch ----------------------------------
extern "C" void kernel_launch(void* const* d_in, const int* in_sizes, int n_in,
                              void* d_out, int out_size)
{
    const int*   ids  = (const int*)d_in[0];
    const int*   sp   = (const int*)d_in[1];
    const float* emb  = (const float*)d_in[2];
    const float* Wq   = (const float*)d_in[3];
    const float* bq   = (const float*)d_in[4];
    const float* Wk   = (const float*)d_in[5];
    const float* bk   = (const float*)d_in[6];
    const float* Wv   = (const float*)d_in[7];
    const float* bv   = (const float*)d_in[8];
    const float* Wo   = (const float*)d_in[9];
    const float* bo   = (const float*)d_in[10];
    const float* ln1g = (const float*)d_in[11];
    const float* ln1b = (const float*)d_in[12];
    const float* ln2g = (const float*)d_in[13];
    const float* ln2b = (const float*)d_in[14];
    const float* W1   = (const float*)d_in[15];
    const float* b1   = (const float*)d_in[16];
    const float* W2   = (const float*)d_in[17];
    const float* b2   = (const float*)d_in[18];
    const float* Wf   = (const float*)d_in[19];
    const float* bf   = (const float*)d_in[20];
    float* out = (float*)d_out;

    float *x, *tmp, *bqkv;
    __half *xch, *qkv, *attnc, *ffc, *w;
    cudaGetSymbolAddress((void**)&x,     g_x);
    cudaGetSymbolAddress((void**)&xch,   g_xch);
    cudaGetSymbolAddress((void**)&qkv,   g_qkv);
    cudaGetSymbolAddress((void**)&attnc, g_attnc);
    cudaGetSymbolAddress((void**)&tmp,   g_tmp);
    cudaGetSymbolAddress((void**)&ffc,   g_ffc);
    cudaGetSymbolAddress((void**)&w,     g_w);
    cudaGetSymbolAddress((void**)&bqkv,  g_bqkv);

    cudaFuncSetAttribute(gemm_h_kernel, cudaFuncAttributeMaxDynamicSharedMemorySize, GEMM_SMEM);

    prep_all_kernel<<<PREP_TILES, dim3(32, 8)>>>(Wq, Wk, Wv, Wo, W1, W2, Wf, w);
    cvt_bias_kernel<<<(Lz * QKVN) / 256, 256>>>(bq, bk, bv, bqkv);
    embed_kernel<<<Mz, 256>>>(ids, emb, x, xch);

    for (int l = 0; l < Lz; ++l) {
        gemm_h_kernel<<<dim3(Mz / 128, QKVN / 128), 256, GEMM_SMEM>>>(
            xch, w + OFF_QKV + (size_t)l * Hz * QKVN, bqkv + l * QKVN, qkv,
            Mz, QKVN, Hz, 0, sp);

        attn_h_kernel<<<dim3(Sz / 64, Bz * NHz), 128>>>(qkv, attnc, sp);

        gemm_h_kernel<<<dim3(Mz / 128, Hz / 128), 256, GEMM_SMEM>>>(
            attnc, w + OFF_WO + (size_t)l * Hz * Hz, bo + l * Hz, tmp,
            Mz, Hz, Hz, 3, sp);
        add_ln_kernel<<<Mz, 256>>>(x, xch, tmp, ln1g + l * Hz, ln1b + l * Hz);

        gemm_h_kernel<<<dim3(Mz / 128, DFz / 128), 256, GEMM_SMEM>>>(
            xch, w + OFF_W1 + (size_t)l * Hz * DFz, b1 + l * DFz, ffc,
            Mz, DFz, Hz, 1, sp);
        gemm_h_kernel<<<dim3(Mz / 128, Hz / 128), 256, GEMM_SMEM>>>(
            ffc, w + OFF_W2 + (size_t)l * DFz * Hz, b2 + l * Hz, tmp,
            Mz, Hz, DFz, 3, sp);
        add_ln_kernel<<<Mz, 256>>>(x, xch, tmp, ln2g + l * Hz, ln2b + l * Hz);
    }

    gemm_h_kernel<<<dim3(Mz / 128, Vz / 128), 256, GEMM_SMEM>>>(
        xch, w + OFF_WF, bf, out, Mz, Vz, Hz, 2, sp);
}

// round 13
// speedup vs baseline: 1.1914x; 1.0320x over previous
#include <cuda_runtime.h>
#include <cuda_fp16.h>
#include <math.h>
#include <stdint.h>

// ---------------------------------------------------------------------------
// TidalTransformer: B=4, S=1024, H=1024, NH=16, DK=64, DF=4096, L=4, V=32000
// Round 13: attention rebuild (cp.async K/V double-buffer, ldmatrix.trans V,
//           register-resident P) + R12 GEMM/prep/LN.
// ---------------------------------------------------------------------------

#define Bz   4
#define Sz   1024
#define Hz   1024
#define NHz  16
#define DKz  64
#define DFz  4096
#define Lz   4
#define Vz   32000
#define Mz   (Bz * Sz)
#define QKVN 3072

// ------------------------- scratch (device globals) ------------------------
__device__ float  g_x   [(size_t)Mz * Hz];
__device__ __half g_xch [(size_t)Mz * Hz];
__device__ __half g_qkv [(size_t)Mz * QKVN];
__device__ __half g_attnc[(size_t)Mz * Hz];
__device__ float  g_tmp [(size_t)Mz * Hz];
__device__ __half g_ffc [(size_t)Mz * DFz];

#define OFF_QKV 0
#define OFF_WO  ((size_t)12582912)
#define OFF_W1  ((size_t)16777216)
#define OFF_W2  ((size_t)33554432)
#define OFF_WF  ((size_t)50331648)
__device__ __half g_w[(size_t)83099648];
__device__ float  g_bqkv[Lz * QKVN];

// ----------------------- merged weight prep --------------------------------
#define PREP_TILES 81152

__global__ void prep_all_kernel(const float* __restrict__ Wq, const float* __restrict__ Wk,
                                const float* __restrict__ Wv, const float* __restrict__ Wo,
                                const float* __restrict__ W1, const float* __restrict__ W2,
                                const float* __restrict__ Wf, __half* __restrict__ w)
{
    __shared__ float t[32][33];
    int idx = blockIdx.x;
    const float* src;
    __half* dst;
    int K, N;

    if (idx < 4096) {
        int l = idx >> 10; idx &= 1023;
        src = Wq + (size_t)l * Hz * Hz; dst = w + OFF_QKV + (size_t)l * Hz * QKVN;
        K = Hz; N = Hz;
    } else if (idx < 8192) {
        idx -= 4096; int l = idx >> 10; idx &= 1023;
        src = Wk + (size_t)l * Hz * Hz;
        dst = w + OFF_QKV + (size_t)l * Hz * QKVN + (size_t)1024 * Hz;
        K = Hz; N = Hz;
    } else if (idx < 12288) {
        idx -= 8192; int l = idx >> 10; idx &= 1023;
        src = Wv + (size_t)l * Hz * Hz;
        dst = w + OFF_QKV + (size_t)l * Hz * QKVN + (size_t)2048 * Hz;
        K = Hz; N = Hz;
    } else if (idx < 16384) {
        idx -= 12288; int l = idx >> 10; idx &= 1023;
        src = Wo + (size_t)l * Hz * Hz; dst = w + OFF_WO + (size_t)l * Hz * Hz;
        K = Hz; N = Hz;
    } else if (idx < 32768) {
        idx -= 16384; int l = idx >> 12; idx &= 4095;
        src = W1 + (size_t)l * Hz * DFz; dst = w + OFF_W1 + (size_t)l * Hz * DFz;
        K = Hz; N = DFz;
    } else if (idx < 49152) {
        idx -= 32768; int l = idx >> 12; idx &= 4095;
        src = W2 + (size_t)l * DFz * Hz; dst = w + OFF_W2 + (size_t)l * DFz * Hz;
        K = DFz; N = Hz;
    } else {
        idx -= 49152;
        src = Wf; dst = w + OFF_WF;
        K = Hz; N = Vz;
    }

    int nt = N >> 5;
    int kb = (idx / nt) * 32, nb = (idx % nt) * 32;
    int tx = threadIdx.x, ty = threadIdx.y;
    #pragma unroll
    for (int i = 0; i < 4; i++)
        t[ty + i * 8][tx] = src[(size_t)(kb + ty + i * 8) * N + nb + tx];
    __syncthreads();
    #pragma unroll
    for (int i = 0; i < 4; i++)
        dst[(size_t)(nb + ty + i * 8) * K + kb + tx] = __float2half_rn(t[tx][ty + i * 8]);
}

__global__ void cvt_bias_kernel(const float* __restrict__ bq, const float* __restrict__ bk,
                                const float* __restrict__ bv, float* __restrict__ dst)
{
    int i = blockIdx.x * 256 + threadIdx.x;
    int n = i % QKVN, l = i / QKVN;
    float v;
    if (n < 1024)       v = bq[l * 1024 + n];
    else if (n < 2048)  v = bk[l * 1024 + n - 1024];
    else                v = bv[l * 1024 + n - 2048];
    dst[i] = v;
}

// ------------------------------- embedding ---------------------------------
__global__ void embed_kernel(const int* __restrict__ ids,
                             const float* __restrict__ emb,
                             float* __restrict__ x, __half* __restrict__ xch)
{
    int row = blockIdx.x;
    int tid = threadIdx.x;
    int id  = ids[row];
    float4 v = *(const float4*)(emb + (size_t)id * Hz + tid * 4);
    v.x *= 32.0f; v.y *= 32.0f; v.z *= 32.0f; v.w *= 32.0f;
    *(float4*)(x + (size_t)row * Hz + tid * 4) = v;
    *(__half2*)(xch + (size_t)row * Hz + tid * 4)     = __floats2half2_rn(v.x, v.y);
    *(__half2*)(xch + (size_t)row * Hz + tid * 4 + 2) = __floats2half2_rn(v.z, v.w);
}

// ---------------------------- mma / ldmatrix -------------------------------
__device__ __forceinline__ void mmah2(float* c, const uint32_t* a,
                                      uint32_t b0, uint32_t b1) {
    asm volatile(
        "mma.sync.aligned.m16n8k16.row.col.f32.f16.f16.f32 "
        "{%0,%1,%2,%3},{%4,%5,%6,%7},{%8,%9},{%0,%1,%2,%3};"
        : "+f"(c[0]), "+f"(c[1]), "+f"(c[2]), "+f"(c[3])
        : "r"(a[0]), "r"(a[1]), "r"(a[2]), "r"(a[3]), "r"(b0), "r"(b1));
}
__device__ __forceinline__ void ldsm4(uint32_t addr, uint32_t& r0, uint32_t& r1,
                                      uint32_t& r2, uint32_t& r3) {
    asm volatile("ldmatrix.sync.aligned.m8n8.x4.shared.b16 {%0,%1,%2,%3}, [%4];"
                 : "=r"(r0), "=r"(r1), "=r"(r2), "=r"(r3) : "r"(addr));
}
__device__ __forceinline__ void ldsm4t(uint32_t addr, uint32_t& r0, uint32_t& r1,
                                       uint32_t& r2, uint32_t& r3) {
    asm volatile("ldmatrix.sync.aligned.m8n8.x4.trans.shared.b16 {%0,%1,%2,%3}, [%4];"
                 : "=r"(r0), "=r"(r1), "=r"(r2), "=r"(r3) : "r"(addr));
}
__device__ __forceinline__ void cpasync16(uint32_t dst, const void* src) {
    asm volatile("cp.async.cg.shared.global [%0], [%1], 16;" :: "r"(dst), "l"(src));
}

// ------------------ fp16 GEMM: 128x128 tile, BK=64, 3-stage ----------------
#define HSTR 72
#define TILE_H (128 * HSTR)
#define GEMM_SMEM (6 * TILE_H * 2)

__global__ __launch_bounds__(256, 2)
void gemm_h_kernel(const __half* __restrict__ A, const __half* __restrict__ Wt,
                   const float* __restrict__ bias, void* __restrict__ Cv,
                   int M, int N, int K, int op, const int* __restrict__ start_pos)
{
    extern __shared__ __half hsm[];
    int tid = threadIdx.x, lane = tid & 31, warp = tid >> 5;
    int wm = warp & 1, wn = warp >> 1;
    int m0 = blockIdx.x * 128, n0 = blockIdx.y * 128;

    int crow = tid >> 1;
    int cc16 = (tid & 1) * 4;
    const __half* aSrc = A  + (size_t)(m0 + crow) * K + cc16 * 8;
    const __half* bSrc = Wt + (size_t)(n0 + crow) * K + cc16 * 8;
    uint32_t asBase = (uint32_t)__cvta_generic_to_shared(hsm);
    uint32_t bsBase = asBase + 3 * TILE_H * 2;
    uint32_t cOff = (uint32_t)(crow * 144 + cc16 * 16);

    float acc[4][4][4];
    #pragma unroll
    for (int i = 0; i < 4; i++)
        #pragma unroll
        for (int j = 0; j < 4; j++)
            #pragma unroll
            for (int r = 0; r < 4; r++) acc[i][j][r] = 0.f;

    int KT = K >> 6;

    #pragma unroll
    for (int s = 0; s < 2; s++) {
        int kk = s * 64;
        #pragma unroll
        for (int i = 0; i < 4; i++)
            cpasync16(asBase + s * (TILE_H * 2) + cOff + i * 16, aSrc + kk + i * 8);
        #pragma unroll
        for (int i = 0; i < 4; i++)
            cpasync16(bsBase + s * (TILE_H * 2) + cOff + i * 16, bSrc + kk + i * 8);
        asm volatile("cp.async.commit_group;");
    }

    uint32_t aLd = (uint32_t)((wm * 64 + (lane & 15)) * 144 + (lane >> 4) * 16);
    uint32_t bLd = (uint32_t)((wn * 32 + (lane & 15)) * 144 + (lane >> 4) * 16);

    for (int kt = 0; kt < KT; ++kt) {
        asm volatile("cp.async.wait_group 1;" ::: "memory");
        __syncthreads();

        uint32_t aSB = asBase + (kt % 3) * (TILE_H * 2);
        uint32_t bSB = bsBase + (kt % 3) * (TILE_H * 2);
        bool doPf = (kt + 2 < KT);
        int s2 = (kt + 2) % 3;
        int kk2 = (kt + 2) * 64;

        #pragma unroll
        for (int ks = 0; ks < 4; ++ks) {
            uint32_t br[2][4];
            #pragma unroll
            for (int p = 0; p < 2; p++)
                ldsm4(bSB + bLd + p * 2304 + ks * 32,
                      br[p][0], br[p][1], br[p][2], br[p][3]);

            uint32_t aCur[4], aNext[4];
            ldsm4(aSB + aLd + ks * 32, aCur[0], aCur[1], aCur[2], aCur[3]);

            #pragma unroll
            for (int im = 0; im < 4; im++) {
                if (im < 3)
                    ldsm4(aSB + aLd + (im + 1) * 2304 + ks * 32,
                          aNext[0], aNext[1], aNext[2], aNext[3]);
                mmah2(acc[im][0], aCur, br[0][0], br[0][2]);
                mmah2(acc[im][1], aCur, br[0][1], br[0][3]);
                mmah2(acc[im][2], aCur, br[1][0], br[1][2]);
                mmah2(acc[im][3], aCur, br[1][1], br[1][3]);
                #pragma unroll
                for (int r = 0; r < 4; r++) aCur[r] = aNext[r];
            }

            if (ks == 0 && doPf) {
                #pragma unroll
                for (int i = 0; i < 4; i++)
                    cpasync16(asBase + s2 * (TILE_H * 2) + cOff + i * 16,
                              aSrc + kk2 + i * 8);
            }
            if (ks == 1) {
                if (doPf) {
                    #pragma unroll
                    for (int i = 0; i < 4; i++)
                        cpasync16(bsBase + s2 * (TILE_H * 2) + cOff + i * 16,
                                  bSrc + kk2 + i * 8);
                }
                asm volatile("cp.async.commit_group;");
            }
        }
    }

    int rbase = m0 + wm * 64 + (lane >> 2);
    int cbase = n0 + wn * 32 + ((lane & 3) << 1);
    #pragma unroll
    for (int im = 0; im < 4; im++) {
        #pragma unroll
        for (int hh = 0; hh < 2; hh++) {
            int row = rbase + im * 16 + hh * 8;
            bool zero = false;
            if (op == 2) zero = (row & 1023) < start_pos[row >> 10];
            #pragma unroll
            for (int in = 0; in < 4; in++) {
                int col = cbase + in * 8;
                float v0 = acc[im][in][hh * 2 + 0] + bias[col];
                float v1 = acc[im][in][hh * 2 + 1] + bias[col + 1];
                if (op == 1) {
                    v0 = 0.5f * v0 * (1.0f + erff(v0 * 0.70710678118654752f));
                    v1 = 0.5f * v1 * (1.0f + erff(v1 * 0.70710678118654752f));
                }
                if (op == 0 || op == 1) {
                    *(__half2*)((__half*)Cv + (size_t)row * N + col) =
                        __floats2half2_rn(v0, v1);
                } else {
                    if (zero) { v0 = 0.f; v1 = 0.f; }
                    float2 o; o.x = v0; o.y = v1;
                    *(float2*)((float*)Cv + (size_t)row * N + col) = o;
                }
            }
        }
    }
}

// ------- fp16 flash attention: cp.async double-buffer, register P ----------
#define AH 72
#define ATILE (64 * AH)   // halves per tile

__global__ __launch_bounds__(128)
void attn_h_kernel(const __half* __restrict__ QKV, __half* __restrict__ O,
                   const int* __restrict__ start_pos)
{
    __shared__ __half sQ[ATILE];
    __shared__ __half sK[2][ATILE];
    __shared__ __half sV[2][ATILE];

    int tid = threadIdx.x, lane = tid & 31, warp = tid >> 5;
    int qt = blockIdx.x, bh = blockIdx.y;
    int b = bh >> 4, h = bh & 15;
    int sp = start_pos[b];
    float slope = exp2f(-0.5f * (float)(h + 1));
    int brow = b * Sz;

    const __half* Qg = QKV + h * 64;
    const __half* Kg = QKV + 1024 + h * 64;
    const __half* Vg = QKV + 2048 + h * 64;

    uint32_t sQb = (uint32_t)__cvta_generic_to_shared(sQ);
    uint32_t sKb[2] = { (uint32_t)__cvta_generic_to_shared(sK[0]),
                        (uint32_t)__cvta_generic_to_shared(sK[1]) };
    uint32_t sVb[2] = { (uint32_t)__cvta_generic_to_shared(sV[0]),
                        (uint32_t)__cvta_generic_to_shared(sV[1]) };

    // copy geometry for K/V tiles: 512 16B-chunks each, 4 per thread
    int crow = tid >> 1;                // rows 0..63 (two threads/row)
    // (each thread does rows crow with chunks (tid&1)*4..+3)
    int cch = (tid & 1) * 4;

    const __half2 hscale = __float2half2_rn(0.125f);
    for (int i = tid; i < 64 * 16; i += 128) {
        int row = i >> 4, d4 = (i & 15) * 4;
        uint2 u = *(const uint2*)(Qg + (size_t)(brow + qt * 64 + row) * QKVN + d4);
        __half2 h0 = __hmul2(*(__half2*)&u.x, hscale);
        __half2 h1 = __hmul2(*(__half2*)&u.y, hscale);
        uint2 o; o.x = *(uint32_t*)&h0; o.y = *(uint32_t*)&h1;
        *(uint2*)(sQ + row * AH + d4) = o;
    }

    int ktmax = (qt * 64 >= sp) ? qt : 15;

    // prologue: load tile 0
    {
        const __half* kp = Kg + (size_t)(brow + crow) * QKVN + cch * 8;
        const __half* vp = Vg + (size_t)(brow + crow) * QKVN + cch * 8;
        uint32_t doff = (uint32_t)(crow * 144 + cch * 16);
        #pragma unroll
        for (int i = 0; i < 4; i++) {
            cpasync16(sKb[0] + doff + i * 16, kp + i * 8);
            cpasync16(sVb[0] + doff + i * 16, vp + i * 8);
        }
        asm volatile("cp.async.commit_group;");
    }

    int qrow = warp * 16 + (lane >> 2);
    int cA   = lane & 3;
    int ig0 = qt * 64 + qrow, ig1 = ig0 + 8;

    uint32_t fragQ = (uint32_t)((warp * 16 + (lane & 15)) * 144 + (lane >> 4) * 16);
    uint32_t fragK = (uint32_t)((lane & 15) * 144 + (lane >> 4) * 16);
    uint32_t fragV = (uint32_t)((lane & 15) * 144 + (lane >> 4) * 16);

    float m0 = -1e30f, m1 = -1e30f, l0 = 0.f, l1 = 0.f;
    float oacc[8][4];
    #pragma unroll
    for (int n = 0; n < 8; n++)
        #pragma unroll
        for (int r = 0; r < 4; r++) oacc[n][r] = 0.f;

    for (int kt = 0; kt <= ktmax; ++kt) {
        int s = kt & 1;
        __syncthreads();   // previous compute on stage s^1 done before refill

        if (kt + 1 <= ktmax) {
            int s1 = (kt + 1) & 1;
            const __half* kp = Kg + (size_t)(brow + (kt + 1) * 64 + crow) * QKVN + cch * 8;
            const __half* vp = Vg + (size_t)(brow + (kt + 1) * 64 + crow) * QKVN + cch * 8;
            uint32_t doff = (uint32_t)(crow * 144 + cch * 16);
            #pragma unroll
            for (int i = 0; i < 4; i++) {
                cpasync16(sKb[s1] + doff + i * 16, kp + i * 8);
                cpasync16(sVb[s1] + doff + i * 16, vp + i * 8);
            }
            asm volatile("cp.async.commit_group;");
            asm volatile("cp.async.wait_group 1;" ::: "memory");
        } else {
            asm volatile("cp.async.wait_group 0;" ::: "memory");
        }
        __syncthreads();   // tile kt visible to all

        // ---- scores = Q @ K^T ----
        float sacc[8][4];
        #pragma unroll
        for (int n = 0; n < 8; n++)
            #pragma unroll
            for (int r = 0; r < 4; r++) sacc[n][r] = 0.f;

        #pragma unroll
        for (int ks = 0; ks < 4; ++ks) {
            uint32_t af[4], br[4][4];
            ldsm4(sQb + fragQ + ks * 32, af[0], af[1], af[2], af[3]);
            #pragma unroll
            for (int p = 0; p < 4; p++)
                ldsm4(sKb[s] + fragK + p * 2304 + ks * 32,
                      br[p][0], br[p][1], br[p][2], br[p][3]);
            #pragma unroll
            for (int n = 0; n < 8; n++)
                mmah2(sacc[n], af, br[n >> 1][n & 1], br[n >> 1][(n & 1) + 2]);
        }

        // ---- alibi + mask ----
        #pragma unroll
        for (int n = 0; n < 8; n++) {
            int jg = kt * 64 + n * 8 + cA * 2;
            #pragma unroll
            for (int half = 0; half < 2; half++) {
                int j = jg + half;
                float al = slope * (float)(j - sp);
                bool ok0 = (j <= ig0) || (ig0 < sp) || (j < sp);
                bool ok1 = (j <= ig1) || (ig1 < sp) || (j < sp);
                sacc[n][half]     = ok0 ? sacc[n][half]     + al : -1e30f;
                sacc[n][half + 2] = ok1 ? sacc[n][half + 2] + al : -1e30f;
            }
        }

        // ---- row max ----
        float t0 = -1e30f, t1 = -1e30f;
        #pragma unroll
        for (int n = 0; n < 8; n++) {
            t0 = fmaxf(t0, fmaxf(sacc[n][0], sacc[n][1]));
            t1 = fmaxf(t1, fmaxf(sacc[n][2], sacc[n][3]));
        }
        t0 = fmaxf(t0, __shfl_xor_sync(0xffffffffu, t0, 1));
        t0 = fmaxf(t0, __shfl_xor_sync(0xffffffffu, t0, 2));
        t1 = fmaxf(t1, __shfl_xor_sync(0xffffffffu, t1, 1));
        t1 = fmaxf(t1, __shfl_xor_sync(0xffffffffu, t1, 2));

        float mn0 = fmaxf(m0, t0), mn1 = fmaxf(m1, t1);
        float scl0 = __expf(m0 - mn0), scl1 = __expf(m1 - mn1);
        m0 = mn0; m1 = mn1;

        // ---- exp to fp16 (kept in registers as PV A-fragments) ----
        uint32_t hpk[8][2];
        float ls0 = 0.f, ls1 = 0.f;
        #pragma unroll
        for (int n = 0; n < 8; n++) {
            __half2 hp0 = __floats2half2_rn(__expf(sacc[n][0] - mn0),
                                            __expf(sacc[n][1] - mn0));
            __half2 hp1 = __floats2half2_rn(__expf(sacc[n][2] - mn1),
                                            __expf(sacc[n][3] - mn1));
            float2 f0 = __half22float2(hp0);
            float2 f1 = __half22float2(hp1);
            ls0 += f0.x + f0.y;
            ls1 += f1.x + f1.y;
            hpk[n][0] = *(uint32_t*)&hp0;
            hpk[n][1] = *(uint32_t*)&hp1;
        }
        ls0 += __shfl_xor_sync(0xffffffffu, ls0, 1);
        ls0 += __shfl_xor_sync(0xffffffffu, ls0, 2);
        ls1 += __shfl_xor_sync(0xffffffffu, ls1, 1);
        ls1 += __shfl_xor_sync(0xffffffffu, ls1, 2);
        l0 = l0 * scl0 + ls0;
        l1 = l1 * scl1 + ls1;

        #pragma unroll
        for (int n = 0; n < 8; n++) {
            oacc[n][0] *= scl0; oacc[n][1] *= scl0;
            oacc[n][2] *= scl1; oacc[n][3] *= scl1;
        }

        // ---- O += P @ V (P from regs, V via ldmatrix.trans) ----
        #pragma unroll
        for (int ks = 0; ks < 4; ++ks) {
            uint32_t af[4] = { hpk[2 * ks][0], hpk[2 * ks][1],
                               hpk[2 * ks + 1][0], hpk[2 * ks + 1][1] };
            #pragma unroll
            for (int p = 0; p < 4; p++) {
                uint32_t r0, r1, r2, r3;
                ldsm4t(sVb[s] + fragV + ks * 16 * 144 + p * 32, r0, r1, r2, r3);
                mmah2(oacc[2 * p],     af, r0, r1);
                mmah2(oacc[2 * p + 1], af, r2, r3);
            }
        }
    }

    float inv0 = 1.f / l0, inv1 = 1.f / l1;
    size_t orow0 = (size_t)(brow + qt * 64 + qrow) * Hz + h * 64;
    size_t orow1 = orow0 + (size_t)8 * Hz;
    #pragma unroll
    for (int n = 0; n < 8; n++) {
        int col = n * 8 + cA * 2;
        *(__half2*)(O + orow0 + col) = __floats2half2_rn(oacc[n][0] * inv0, oacc[n][1] * inv0);
        *(__half2*)(O + orow1 + col) = __floats2half2_rn(oacc[n][2] * inv1, oacc[n][3] * inv1);
    }
}

// ------------------------ fused residual + layernorm -----------------------
__inline__ __device__ float warp_sum(float v) {
    #pragma unroll
    for (int o = 16; o; o >>= 1) v += __shfl_xor_sync(0xffffffffu, v, o);
    return v;
}

__global__ void add_ln_kernel(float* __restrict__ x, __half* __restrict__ xch,
                              const float* __restrict__ t,
                              const float* __restrict__ g, const float* __restrict__ b)
{
    int row = blockIdx.x;
    int tid = threadIdx.x;
    size_t off = (size_t)row * Hz + tid * 4;

    float4 xv = *(const float4*)(x + off);
    float4 tv = *(const float4*)(t + off);
    float v0 = xv.x + tv.x, v1 = xv.y + tv.y, v2 = xv.z + tv.z, v3 = xv.w + tv.w;

    float s  = v0 + v1 + v2 + v3;
    float s2 = v0 * v0 + v1 * v1 + v2 * v2 + v3 * v3;

    __shared__ float sh1[8], sh2[8];
    int lane = tid & 31, wid = tid >> 5;
    s  = warp_sum(s);
    s2 = warp_sum(s2);
    if (lane == 0) { sh1[wid] = s; sh2[wid] = s2; }
    __syncthreads();
    if (wid == 0) {
        float a = (lane < 8) ? sh1[lane] : 0.f;
        float c = (lane < 8) ? sh2[lane] : 0.f;
        a = warp_sum(a);
        c = warp_sum(c);
        if (lane == 0) { sh1[0] = a; sh2[0] = c; }
    }
    __syncthreads();

    float mu  = sh1[0] * (1.0f / Hz);
    float var = sh2[0] * (1.0f / Hz) - mu * mu;
    float inv = rsqrtf(var + 1e-5f);

    int cbase = tid * 4;
    float4 gv = *(const float4*)(g + cbase);
    float4 bv = *(const float4*)(b + cbase);
    float4 out;
    out.x = (v0 - mu) * inv * gv.x + bv.x;
    out.y = (v1 - mu) * inv * gv.y + bv.y;
    out.z = (v2 - mu) * inv * gv.z + bv.z;
    out.w = (v3 - mu) * inv * gv.w + bv.w;
    *(float4*)(x + off) = out;
    *(__half2*)(xch + off)     = __floats2half2_rn(out.x, out.y);
    *(__half2*)(xch + off + 2) = __floats2half2_rn(out.z, out.w);
}

// --------------------------------- launch ----------------------------------
extern "C" void kernel_launch(void* const* d_in, const int* in_sizes, int n_in,
                              void* d_out, int out_size)
{
    const int*   ids  = (const int*)d_in[0];
    const int*   sp   = (const int*)d_in[1];
    const float* emb  = (const float*)d_in[2];
    const float* Wq   = (const float*)d_in[3];
    const float* bq   = (const float*)d_in[4];
    const float* Wk   = (const float*)d_in[5];
    const float* bk   = (const float*)d_in[6];
    const float* Wv   = (const float*)d_in[7];
    const float* bv   = (const float*)d_in[8];
    const float* Wo   = (const float*)d_in[9];
    const float* bo   = (const float*)d_in[10];
    const float* ln1g = (const float*)d_in[11];
    const float* ln1b = (const float*)d_in[12];
    const float* ln2g = (const float*)d_in[13];
    const float* ln2b = (const float*)d_in[14];
    const float* W1   = (const float*)d_in[15];
    const float* b1   = (const float*)d_in[16];
    const float* W2   = (const float*)d_in[17];
    const float* b2   = (const float*)d_in[18];
    const float* Wf   = (const float*)d_in[19];
    const float* bf   = (const float*)d_in[20];
    float* out = (float*)d_out;

    float *x, *tmp, *bqkv;
    __half *xch, *qkv, *attnc, *ffc, *w;
    cudaGetSymbolAddress((void**)&x,     g_x);
    cudaGetSymbolAddress((void**)&xch,   g_xch);
    cudaGetSymbolAddress((void**)&qkv,   g_qkv);
    cudaGetSymbolAddress((void**)&attnc, g_attnc);
    cudaGetSymbolAddress((void**)&tmp,   g_tmp);
    cudaGetSymbolAddress((void**)&ffc,   g_ffc);
    cudaGetSymbolAddress((void**)&w,     g_w);
    cudaGetSymbolAddress((void**)&bqkv,  g_bqkv);

    cudaFuncSetAttribute(gemm_h_kernel, cudaFuncAttributeMaxDynamicSharedMemorySize, GEMM_SMEM);

    prep_all_kernel<<<PREP_TILES, dim3(32, 8)>>>(Wq, Wk, Wv, Wo, W1, W2, Wf, w);
    cvt_bias_kernel<<<(Lz * QKVN) / 256, 256>>>(bq, bk, bv, bqkv);
    embed_kernel<<<Mz, 256>>>(ids, emb, x, xch);

    for (int l = 0; l < Lz; ++l) {
        gemm_h_kernel<<<dim3(Mz / 128, QKVN / 128), 256, GEMM_SMEM>>>(
            xch, w + OFF_QKV + (size_t)l * Hz * QKVN, bqkv + l * QKVN, qkv,
            Mz, QKVN, Hz, 0, sp);

        attn_h_kernel<<<dim3(Sz / 64, Bz * NHz), 128>>>(qkv, attnc, sp);

        gemm_h_kernel<<<dim3(Mz / 128, Hz / 128), 256, GEMM_SMEM>>>(
            attnc, w + OFF_WO + (size_t)l * Hz * Hz, bo + l * Hz, tmp,
            Mz, Hz, Hz, 3, sp);
        add_ln_kernel<<<Mz, 256>>>(x, xch, tmp, ln1g + l * Hz, ln1b + l * Hz);

        gemm_h_kernel<<<dim3(Mz / 128, DFz / 128), 256, GEMM_SMEM>>>(
            xch, w + OFF_W1 + (size_t)l * Hz * DFz, b1 + l * DFz, ffc,
            Mz, DFz, Hz, 1, sp);
        gemm_h_kernel<<<dim3(Mz / 128, Hz / 128), 256, GEMM_SMEM>>>(
            ffc, w + OFF_W2 + (size_t)l * DFz * Hz, b2 + l * Hz, tmp,
            Mz, Hz, DFz, 3, sp);
        add_ln_kernel<<<Mz, 256>>>(x, xch, tmp, ln2g + l * Hz, ln2b + l * Hz);
    }

    gemm_h_kernel<<<dim3(Mz / 128, Vz / 128), 256, GEMM_SMEM>>>(
        xch, w + OFF_WF, bf, out, Mz, Vz, Hz, 2, sp);
}

// round 16
// speedup vs baseline: 1.2674x; 1.0638x over previous
#include <cuda_runtime.h>
#include <cuda_fp16.h>
#include <math.h>
#include <stdint.h>

// ---------------------------------------------------------------------------
// TidalTransformer: B=4, S=1024, H=1024, NH=16, DK=64, DF=4096, L=4, V=32000
// Round 14: dual-stream row-split pipelining (batches 0-1 / 2-3 run as two
//           independent overlapped chains) + R13 kernels with row offsets.
// ---------------------------------------------------------------------------

#define Bz   4
#define Sz   1024
#define Hz   1024
#define NHz  16
#define DKz  64
#define DFz  4096
#define Lz   4
#define Vz   32000
#define Mz   (Bz * Sz)
#define QKVN 3072
#define MH   (Mz / 2)     // rows per stream half

// ------------------------- scratch (device globals) ------------------------
__device__ float  g_x   [(size_t)Mz * Hz];
__device__ __half g_xch [(size_t)Mz * Hz];
__device__ __half g_qkv [(size_t)Mz * QKVN];
__device__ __half g_attnc[(size_t)Mz * Hz];
__device__ float  g_tmp [(size_t)Mz * Hz];
__device__ __half g_ffc [(size_t)Mz * DFz];

#define OFF_QKV 0
#define OFF_WO  ((size_t)12582912)
#define OFF_W1  ((size_t)16777216)
#define OFF_W2  ((size_t)33554432)
#define OFF_WF  ((size_t)50331648)
__device__ __half g_w[(size_t)83099648];
__device__ float  g_bqkv[Lz * QKVN];

// ----------------------- merged weight prep --------------------------------
#define PREP_TILES 81152

__global__ void prep_all_kernel(const float* __restrict__ Wq, const float* __restrict__ Wk,
                                const float* __restrict__ Wv, const float* __restrict__ Wo,
                                const float* __restrict__ W1, const float* __restrict__ W2,
                                const float* __restrict__ Wf, __half* __restrict__ w)
{
    __shared__ float t[32][33];
    int idx = blockIdx.x;
    const float* src;
    __half* dst;
    int K, N;

    if (idx < 4096) {
        int l = idx >> 10; idx &= 1023;
        src = Wq + (size_t)l * Hz * Hz; dst = w + OFF_QKV + (size_t)l * Hz * QKVN;
        K = Hz; N = Hz;
    } else if (idx < 8192) {
        idx -= 4096; int l = idx >> 10; idx &= 1023;
        src = Wk + (size_t)l * Hz * Hz;
        dst = w + OFF_QKV + (size_t)l * Hz * QKVN + (size_t)1024 * Hz;
        K = Hz; N = Hz;
    } else if (idx < 12288) {
        idx -= 8192; int l = idx >> 10; idx &= 1023;
        src = Wv + (size_t)l * Hz * Hz;
        dst = w + OFF_QKV + (size_t)l * Hz * QKVN + (size_t)2048 * Hz;
        K = Hz; N = Hz;
    } else if (idx < 16384) {
        idx -= 12288; int l = idx >> 10; idx &= 1023;
        src = Wo + (size_t)l * Hz * Hz; dst = w + OFF_WO + (size_t)l * Hz * Hz;
        K = Hz; N = Hz;
    } else if (idx < 32768) {
        idx -= 16384; int l = idx >> 12; idx &= 4095;
        src = W1 + (size_t)l * Hz * DFz; dst = w + OFF_W1 + (size_t)l * Hz * DFz;
        K = Hz; N = DFz;
    } else if (idx < 49152) {
        idx -= 32768; int l = idx >> 12; idx &= 4095;
        src = W2 + (size_t)l * DFz * Hz; dst = w + OFF_W2 + (size_t)l * DFz * Hz;
        K = DFz; N = Hz;
    } else {
        idx -= 49152;
        src = Wf; dst = w + OFF_WF;
        K = Hz; N = Vz;
    }

    int nt = N >> 5;
    int kb = (idx / nt) * 32, nb = (idx % nt) * 32;
    int tx = threadIdx.x, ty = threadIdx.y;
    #pragma unroll
    for (int i = 0; i < 4; i++)
        t[ty + i * 8][tx] = src[(size_t)(kb + ty + i * 8) * N + nb + tx];
    __syncthreads();
    #pragma unroll
    for (int i = 0; i < 4; i++)
        dst[(size_t)(nb + ty + i * 8) * K + kb + tx] = __float2half_rn(t[tx][ty + i * 8]);
}

__global__ void cvt_bias_kernel(const float* __restrict__ bq, const float* __restrict__ bk,
                                const float* __restrict__ bv, float* __restrict__ dst)
{
    int i = blockIdx.x * 256 + threadIdx.x;
    int n = i % QKVN, l = i / QKVN;
    float v;
    if (n < 1024)       v = bq[l * 1024 + n];
    else if (n < 2048)  v = bk[l * 1024 + n - 1024];
    else                v = bv[l * 1024 + n - 2048];
    dst[i] = v;
}

// ------------------------------- embedding ---------------------------------
__global__ void embed_kernel(const int* __restrict__ ids,
                             const float* __restrict__ emb,
                             float* __restrict__ x, __half* __restrict__ xch)
{
    int row = blockIdx.x;
    int tid = threadIdx.x;
    int id  = ids[row];
    float4 v = *(const float4*)(emb + (size_t)id * Hz + tid * 4);
    v.x *= 32.0f; v.y *= 32.0f; v.z *= 32.0f; v.w *= 32.0f;
    *(float4*)(x + (size_t)row * Hz + tid * 4) = v;
    *(__half2*)(xch + (size_t)row * Hz + tid * 4)     = __floats2half2_rn(v.x, v.y);
    *(__half2*)(xch + (size_t)row * Hz + tid * 4 + 2) = __floats2half2_rn(v.z, v.w);
}

// ---------------------------- mma / ldmatrix -------------------------------
__device__ __forceinline__ void mmah2(float* c, const uint32_t* a,
                                      uint32_t b0, uint32_t b1) {
    asm volatile(
        "mma.sync.aligned.m16n8k16.row.col.f32.f16.f16.f32 "
        "{%0,%1,%2,%3},{%4,%5,%6,%7},{%8,%9},{%0,%1,%2,%3};"
        : "+f"(c[0]), "+f"(c[1]), "+f"(c[2]), "+f"(c[3])
        : "r"(a[0]), "r"(a[1]), "r"(a[2]), "r"(a[3]), "r"(b0), "r"(b1));
}
__device__ __forceinline__ void ldsm4(uint32_t addr, uint32_t& r0, uint32_t& r1,
                                      uint32_t& r2, uint32_t& r3) {
    asm volatile("ldmatrix.sync.aligned.m8n8.x4.shared.b16 {%0,%1,%2,%3}, [%4];"
                 : "=r"(r0), "=r"(r1), "=r"(r2), "=r"(r3) : "r"(addr));
}
__device__ __forceinline__ void ldsm4t(uint32_t addr, uint32_t& r0, uint32_t& r1,
                                       uint32_t& r2, uint32_t& r3) {
    asm volatile("ldmatrix.sync.aligned.m8n8.x4.trans.shared.b16 {%0,%1,%2,%3}, [%4];"
                 : "=r"(r0), "=r"(r1), "=r"(r2), "=r"(r3) : "r"(addr));
}
__device__ __forceinline__ void cpasync16(uint32_t dst, const void* src) {
    asm volatile("cp.async.cg.shared.global [%0], [%1], 16;" :: "r"(dst), "l"(src));
}

// ------------------ fp16 GEMM: 128x128 tile, BK=64, 3-stage ----------------
#define HSTR 72
#define TILE_H (128 * HSTR)
#define GEMM_SMEM (6 * TILE_H * 2)

__global__ __launch_bounds__(256, 2)
void gemm_h_kernel(const __half* __restrict__ A, const __half* __restrict__ Wt,
                   const float* __restrict__ bias, void* __restrict__ Cv,
                   int mBase, int N, int K, int op, const int* __restrict__ start_pos)
{
    extern __shared__ __half hsm[];
    int tid = threadIdx.x, lane = tid & 31, warp = tid >> 5;
    int wm = warp & 1, wn = warp >> 1;
    int m0 = mBase + blockIdx.x * 128, n0 = blockIdx.y * 128;

    int crow = tid >> 1;
    int cc16 = (tid & 1) * 4;
    const __half* aSrc = A  + (size_t)(m0 + crow) * K + cc16 * 8;
    const __half* bSrc = Wt + (size_t)(n0 + crow) * K + cc16 * 8;
    uint32_t asBase = (uint32_t)__cvta_generic_to_shared(hsm);
    uint32_t bsBase = asBase + 3 * TILE_H * 2;
    uint32_t cOff = (uint32_t)(crow * 144 + cc16 * 16);

    float acc[4][4][4];
    #pragma unroll
    for (int i = 0; i < 4; i++)
        #pragma unroll
        for (int j = 0; j < 4; j++)
            #pragma unroll
            for (int r = 0; r < 4; r++) acc[i][j][r] = 0.f;

    int KT = K >> 6;

    #pragma unroll
    for (int s = 0; s < 2; s++) {
        int kk = s * 64;
        #pragma unroll
        for (int i = 0; i < 4; i++)
            cpasync16(asBase + s * (TILE_H * 2) + cOff + i * 16, aSrc + kk + i * 8);
        #pragma unroll
        for (int i = 0; i < 4; i++)
            cpasync16(bsBase + s * (TILE_H * 2) + cOff + i * 16, bSrc + kk + i * 8);
        asm volatile("cp.async.commit_group;");
    }

    uint32_t aLd = (uint32_t)((wm * 64 + (lane & 15)) * 144 + (lane >> 4) * 16);
    uint32_t bLd = (uint32_t)((wn * 32 + (lane & 15)) * 144 + (lane >> 4) * 16);

    for (int kt = 0; kt < KT; ++kt) {
        asm volatile("cp.async.wait_group 1;" ::: "memory");
        __syncthreads();

        uint32_t aSB = asBase + (kt % 3) * (TILE_H * 2);
        uint32_t bSB = bsBase + (kt % 3) * (TILE_H * 2);
        bool doPf = (kt + 2 < KT);
        int s2 = (kt + 2) % 3;
        int kk2 = (kt + 2) * 64;

        #pragma unroll
        for (int ks = 0; ks < 4; ++ks) {
            uint32_t br[2][4];
            #pragma unroll
            for (int p = 0; p < 2; p++)
                ldsm4(bSB + bLd + p * 2304 + ks * 32,
                      br[p][0], br[p][1], br[p][2], br[p][3]);

            uint32_t aCur[4], aNext[4];
            ldsm4(aSB + aLd + ks * 32, aCur[0], aCur[1], aCur[2], aCur[3]);

            #pragma unroll
            for (int im = 0; im < 4; im++) {
                if (im < 3)
                    ldsm4(aSB + aLd + (im + 1) * 2304 + ks * 32,
                          aNext[0], aNext[1], aNext[2], aNext[3]);
                mmah2(acc[im][0], aCur, br[0][0], br[0][2]);
                mmah2(acc[im][1], aCur, br[0][1], br[0][3]);
                mmah2(acc[im][2], aCur, br[1][0], br[1][2]);
                mmah2(acc[im][3], aCur, br[1][1], br[1][3]);
                #pragma unroll
                for (int r = 0; r < 4; r++) aCur[r] = aNext[r];
            }

            if (ks == 0 && doPf) {
                #pragma unroll
                for (int i = 0; i < 4; i++)
                    cpasync16(asBase + s2 * (TILE_H * 2) + cOff + i * 16,
                              aSrc + kk2 + i * 8);
            }
            if (ks == 1) {
                if (doPf) {
                    #pragma unroll
                    for (int i = 0; i < 4; i++)
                        cpasync16(bsBase + s2 * (TILE_H * 2) + cOff + i * 16,
                                  bSrc + kk2 + i * 8);
                }
                asm volatile("cp.async.commit_group;");
            }
        }
    }

    int rbase = m0 + wm * 64 + (lane >> 2);
    int cbase = n0 + wn * 32 + ((lane & 3) << 1);
    #pragma unroll
    for (int im = 0; im < 4; im++) {
        #pragma unroll
        for (int hh = 0; hh < 2; hh++) {
            int row = rbase + im * 16 + hh * 8;
            bool zero = false;
            if (op == 2) zero = (row & 1023) < start_pos[row >> 10];
            #pragma unroll
            for (int in = 0; in < 4; in++) {
                int col = cbase + in * 8;
                float v0 = acc[im][in][hh * 2 + 0] + bias[col];
                float v1 = acc[im][in][hh * 2 + 1] + bias[col + 1];
                if (op == 1) {
                    v0 = 0.5f * v0 * (1.0f + erff(v0 * 0.70710678118654752f));
                    v1 = 0.5f * v1 * (1.0f + erff(v1 * 0.70710678118654752f));
                }
                if (op == 0 || op == 1) {
                    *(__half2*)((__half*)Cv + (size_t)row * N + col) =
                        __floats2half2_rn(v0, v1);
                } else {
                    if (zero) { v0 = 0.f; v1 = 0.f; }
                    float2 o; o.x = v0; o.y = v1;
                    *(float2*)((float*)Cv + (size_t)row * N + col) = o;
                }
            }
        }
    }
}

// ------- fp16 flash attention: cp.async double-buffer, register P ----------
#define AH 72
#define ATILE (64 * AH)

__global__ __launch_bounds__(128)
void attn_h_kernel(const __half* __restrict__ QKV, __half* __restrict__ O,
                   const int* __restrict__ start_pos, int bOff)
{
    __shared__ __half sQ[ATILE];
    __shared__ __half sK[2][ATILE];
    __shared__ __half sV[2][ATILE];

    int tid = threadIdx.x, lane = tid & 31, warp = tid >> 5;
    int qt = blockIdx.x, bh = blockIdx.y;
    int b = bOff + (bh >> 4), h = bh & 15;
    int sp = start_pos[b];
    float slope = exp2f(-0.5f * (float)(h + 1));
    int brow = b * Sz;

    const __half* Qg = QKV + h * 64;
    const __half* Kg = QKV + 1024 + h * 64;
    const __half* Vg = QKV + 2048 + h * 64;

    uint32_t sQb = (uint32_t)__cvta_generic_to_shared(sQ);
    uint32_t sKb[2] = { (uint32_t)__cvta_generic_to_shared(sK[0]),
                        (uint32_t)__cvta_generic_to_shared(sK[1]) };
    uint32_t sVb[2] = { (uint32_t)__cvta_generic_to_shared(sV[0]),
                        (uint32_t)__cvta_generic_to_shared(sV[1]) };

    int crow = tid >> 1;
    int cch = (tid & 1) * 4;

    const __half2 hscale = __float2half2_rn(0.125f);
    for (int i = tid; i < 64 * 16; i += 128) {
        int row = i >> 4, d4 = (i & 15) * 4;
        uint2 u = *(const uint2*)(Qg + (size_t)(brow + qt * 64 + row) * QKVN + d4);
        __half2 h0 = __hmul2(*(__half2*)&u.x, hscale);
        __half2 h1 = __hmul2(*(__half2*)&u.y, hscale);
        uint2 o; o.x = *(uint32_t*)&h0; o.y = *(uint32_t*)&h1;
        *(uint2*)(sQ + row * AH + d4) = o;
    }

    int ktmax = (qt * 64 >= sp) ? qt : 15;

    {
        const __half* kp = Kg + (size_t)(brow + crow) * QKVN + cch * 8;
        const __half* vp = Vg + (size_t)(brow + crow) * QKVN + cch * 8;
        uint32_t doff = (uint32_t)(crow * 144 + cch * 16);
        #pragma unroll
        for (int i = 0; i < 4; i++) {
            cpasync16(sKb[0] + doff + i * 16, kp + i * 8);
            cpasync16(sVb[0] + doff + i * 16, vp + i * 8);
        }
        asm volatile("cp.async.commit_group;");
    }

    int qrow = warp * 16 + (lane >> 2);
    int cA   = lane & 3;
    int ig0 = qt * 64 + qrow, ig1 = ig0 + 8;

    uint32_t fragQ = (uint32_t)((warp * 16 + (lane & 15)) * 144 + (lane >> 4) * 16);
    uint32_t fragK = (uint32_t)((lane & 15) * 144 + (lane >> 4) * 16);
    uint32_t fragV = fragK;

    float m0 = -1e30f, m1 = -1e30f, l0 = 0.f, l1 = 0.f;
    float oacc[8][4];
    #pragma unroll
    for (int n = 0; n < 8; n++)
        #pragma unroll
        for (int r = 0; r < 4; r++) oacc[n][r] = 0.f;

    for (int kt = 0; kt <= ktmax; ++kt) {
        int s = kt & 1;
        __syncthreads();

        if (kt + 1 <= ktmax) {
            int s1 = (kt + 1) & 1;
            const __half* kp = Kg + (size_t)(brow + (kt + 1) * 64 + crow) * QKVN + cch * 8;
            const __half* vp = Vg + (size_t)(brow + (kt + 1) * 64 + crow) * QKVN + cch * 8;
            uint32_t doff = (uint32_t)(crow * 144 + cch * 16);
            #pragma unroll
            for (int i = 0; i < 4; i++) {
                cpasync16(sKb[s1] + doff + i * 16, kp + i * 8);
                cpasync16(sVb[s1] + doff + i * 16, vp + i * 8);
            }
            asm volatile("cp.async.commit_group;");
            asm volatile("cp.async.wait_group 1;" ::: "memory");
        } else {
            asm volatile("cp.async.wait_group 0;" ::: "memory");
        }
        __syncthreads();

        float sacc[8][4];
        #pragma unroll
        for (int n = 0; n < 8; n++)
            #pragma unroll
            for (int r = 0; r < 4; r++) sacc[n][r] = 0.f;

        #pragma unroll
        for (int ks = 0; ks < 4; ++ks) {
            uint32_t af[4], br[4][4];
            ldsm4(sQb + fragQ + ks * 32, af[0], af[1], af[2], af[3]);
            #pragma unroll
            for (int p = 0; p < 4; p++)
                ldsm4(sKb[s] + fragK + p * 2304 + ks * 32,
                      br[p][0], br[p][1], br[p][2], br[p][3]);
            #pragma unroll
            for (int n = 0; n < 8; n++)
                mmah2(sacc[n], af, br[n >> 1][n & 1], br[n >> 1][(n & 1) + 2]);
        }

        #pragma unroll
        for (int n = 0; n < 8; n++) {
            int jg = kt * 64 + n * 8 + cA * 2;
            #pragma unroll
            for (int half = 0; half < 2; half++) {
                int j = jg + half;
                float al = slope * (float)(j - sp);
                bool ok0 = (j <= ig0) || (ig0 < sp) || (j < sp);
                bool ok1 = (j <= ig1) || (ig1 < sp) || (j < sp);
                sacc[n][half]     = ok0 ? sacc[n][half]     + al : -1e30f;
                sacc[n][half + 2] = ok1 ? sacc[n][half + 2] + al : -1e30f;
            }
        }

        float t0 = -1e30f, t1 = -1e30f;
        #pragma unroll
        for (int n = 0; n < 8; n++) {
            t0 = fmaxf(t0, fmaxf(sacc[n][0], sacc[n][1]));
            t1 = fmaxf(t1, fmaxf(sacc[n][2], sacc[n][3]));
        }
        t0 = fmaxf(t0, __shfl_xor_sync(0xffffffffu, t0, 1));
        t0 = fmaxf(t0, __shfl_xor_sync(0xffffffffu, t0, 2));
        t1 = fmaxf(t1, __shfl_xor_sync(0xffffffffu, t1, 1));
        t1 = fmaxf(t1, __shfl_xor_sync(0xffffffffu, t1, 2));

        float mn0 = fmaxf(m0, t0), mn1 = fmaxf(m1, t1);
        float scl0 = __expf(m0 - mn0), scl1 = __expf(m1 - mn1);
        m0 = mn0; m1 = mn1;

        uint32_t hpk[8][2];
        float ls0 = 0.f, ls1 = 0.f;
        #pragma unroll
        for (int n = 0; n < 8; n++) {
            __half2 hp0 = __floats2half2_rn(__expf(sacc[n][0] - mn0),
                                            __expf(sacc[n][1] - mn0));
            __half2 hp1 = __floats2half2_rn(__expf(sacc[n][2] - mn1),
                                            __expf(sacc[n][3] - mn1));
            float2 f0 = __half22float2(hp0);
            float2 f1 = __half22float2(hp1);
            ls0 += f0.x + f0.y;
            ls1 += f1.x + f1.y;
            hpk[n][0] = *(uint32_t*)&hp0;
            hpk[n][1] = *(uint32_t*)&hp1;
        }
        ls0 += __shfl_xor_sync(0xffffffffu, ls0, 1);
        ls0 += __shfl_xor_sync(0xffffffffu, ls0, 2);
        ls1 += __shfl_xor_sync(0xffffffffu, ls1, 1);
        ls1 += __shfl_xor_sync(0xffffffffu, ls1, 2);
        l0 = l0 * scl0 + ls0;
        l1 = l1 * scl1 + ls1;

        #pragma unroll
        for (int n = 0; n < 8; n++) {
            oacc[n][0] *= scl0; oacc[n][1] *= scl0;
            oacc[n][2] *= scl1; oacc[n][3] *= scl1;
        }

        #pragma unroll
        for (int ks = 0; ks < 4; ++ks) {
            uint32_t af[4] = { hpk[2 * ks][0], hpk[2 * ks][1],
                               hpk[2 * ks + 1][0], hpk[2 * ks + 1][1] };
            #pragma unroll
            for (int p = 0; p < 4; p++) {
                uint32_t r0, r1, r2, r3;
                ldsm4t(sVb[s] + fragV + ks * 16 * 144 + p * 32, r0, r1, r2, r3);
                mmah2(oacc[2 * p],     af, r0, r1);
                mmah2(oacc[2 * p + 1], af, r2, r3);
            }
        }
    }

    float inv0 = 1.f / l0, inv1 = 1.f / l1;
    size_t orow0 = (size_t)(brow + qt * 64 + qrow) * Hz + h * 64;
    size_t orow1 = orow0 + (size_t)8 * Hz;
    #pragma unroll
    for (int n = 0; n < 8; n++) {
        int col = n * 8 + cA * 2;
        *(__half2*)(O + orow0 + col) = __floats2half2_rn(oacc[n][0] * inv0, oacc[n][1] * inv0);
        *(__half2*)(O + orow1 + col) = __floats2half2_rn(oacc[n][2] * inv1, oacc[n][3] * inv1);
    }
}

// ------------------------ fused residual + layernorm -----------------------
__inline__ __device__ float warp_sum(float v) {
    #pragma unroll
    for (int o = 16; o; o >>= 1) v += __shfl_xor_sync(0xffffffffu, v, o);
    return v;
}

__global__ void add_ln_kernel(float* __restrict__ x, __half* __restrict__ xch,
                              const float* __restrict__ t,
                              const float* __restrict__ g, const float* __restrict__ b,
                              int rowOff)
{
    int row = rowOff + blockIdx.x;
    int tid = threadIdx.x;
    size_t off = (size_t)row * Hz + tid * 4;

    float4 xv = *(const float4*)(x + off);
    float4 tv = *(const float4*)(t + off);
    float v0 = xv.x + tv.x, v1 = xv.y + tv.y, v2 = xv.z + tv.z, v3 = xv.w + tv.w;

    float s  = v0 + v1 + v2 + v3;
    float s2 = v0 * v0 + v1 * v1 + v2 * v2 + v3 * v3;

    __shared__ float sh1[8], sh2[8];
    int lane = tid & 31, wid = tid >> 5;
    s  = warp_sum(s);
    s2 = warp_sum(s2);
    if (lane == 0) { sh1[wid] = s; sh2[wid] = s2; }
    __syncthreads();
    if (wid == 0) {
        float a = (lane < 8) ? sh1[lane] : 0.f;
        float c = (lane < 8) ? sh2[lane] : 0.f;
        a = warp_sum(a);
        c = warp_sum(c);
        if (lane == 0) { sh1[0] = a; sh2[0] = c; }
    }
    __syncthreads();

    float mu  = sh1[0] * (1.0f / Hz);
    float var = sh2[0] * (1.0f / Hz) - mu * mu;
    float inv = rsqrtf(var + 1e-5f);

    int cbase = tid * 4;
    float4 gv = *(const float4*)(g + cbase);
    float4 bv = *(const float4*)(b + cbase);
    float4 out;
    out.x = (v0 - mu) * inv * gv.x + bv.x;
    out.y = (v1 - mu) * inv * gv.y + bv.y;
    out.z = (v2 - mu) * inv * gv.z + bv.z;
    out.w = (v3 - mu) * inv * gv.w + bv.w;
    *(float4*)(x + off) = out;
    *(__half2*)(xch + off)     = __floats2half2_rn(out.x, out.y);
    *(__half2*)(xch + off + 2) = __floats2half2_rn(out.z, out.w);
}

// --------------------------------- launch ----------------------------------
struct HalfCtx {
    float* x; __half* xch; __half* qkv; __half* attnc; float* tmp; __half* ffc;
    __half* w; float* bqkv; float* out;
    const float *bo, *ln1g, *ln1b, *ln2g, *ln2b, *b1, *b2, *bf;
    const int* sp;
};

static void run_half(cudaStream_t st, const HalfCtx& c, int mBase, int bOff)
{
    for (int l = 0; l < Lz; ++l) {
        gemm_h_kernel<<<dim3(MH / 128, QKVN / 128), 256, GEMM_SMEM, st>>>(
            c.xch, c.w + OFF_QKV + (size_t)l * Hz * QKVN, c.bqkv + l * QKVN, c.qkv,
            mBase, QKVN, Hz, 0, c.sp);

        attn_h_kernel<<<dim3(Sz / 64, (Bz / 2) * NHz), 128, 0, st>>>(
            c.qkv, c.attnc, c.sp, bOff);

        gemm_h_kernel<<<dim3(MH / 128, Hz / 128), 256, GEMM_SMEM, st>>>(
            c.attnc, c.w + OFF_WO + (size_t)l * Hz * Hz, c.bo + l * Hz, c.tmp,
            mBase, Hz, Hz, 3, c.sp);
        add_ln_kernel<<<MH, 256, 0, st>>>(c.x, c.xch, c.tmp,
                                          c.ln1g + l * Hz, c.ln1b + l * Hz, mBase);

        gemm_h_kernel<<<dim3(MH / 128, DFz / 128), 256, GEMM_SMEM, st>>>(
            c.xch, c.w + OFF_W1 + (size_t)l * Hz * DFz, c.b1 + l * DFz, c.ffc,
            mBase, DFz, Hz, 1, c.sp);
        gemm_h_kernel<<<dim3(MH / 128, Hz / 128), 256, GEMM_SMEM, st>>>(
            c.ffc, c.w + OFF_W2 + (size_t)l * DFz * Hz, c.b2 + l * Hz, c.tmp,
            mBase, Hz, DFz, 3, c.sp);
        add_ln_kernel<<<MH, 256, 0, st>>>(c.x, c.xch, c.tmp,
                                          c.ln2g + l * Hz, c.ln2b + l * Hz, mBase);
    }
    gemm_h_kernel<<<dim3(MH / 128, Vz / 128), 256, GEMM_SMEM, st>>>(
        c.xch, c.w + OFF_WF, c.bf, c.out, mBase, Vz, Hz, 2, c.sp);
}

extern "C" void kernel_launch(void* const* d_in, const int* in_sizes, int n_in,
                              void* d_out, int out_size)
{
    const int*   ids  = (const int*)d_in[0];
    const int*   sp   = (const int*)d_in[1];
    const float* emb  = (const float*)d_in[2];
    const float* Wq   = (const float*)d_in[3];
    const float* bq   = (const float*)d_in[4];
    const float* Wk   = (const float*)d_in[5];
    const float* bk   = (const float*)d_in[6];
    const float* Wv   = (const float*)d_in[7];
    const float* bv   = (const float*)d_in[8];
    const float* Wo   = (const float*)d_in[9];
    const float* bo   = (const float*)d_in[10];
    const float* ln1g = (const float*)d_in[11];
    const float* ln1b = (const float*)d_in[12];
    const float* ln2g = (const float*)d_in[13];
    const float* ln2b = (const float*)d_in[14];
    const float* W1   = (const float*)d_in[15];
    const float* b1   = (const float*)d_in[16];
    const float* W2   = (const float*)d_in[17];
    const float* b2   = (const float*)d_in[18];
    const float* Wf   = (const float*)d_in[19];
    const float* bf   = (const float*)d_in[20];
    float* out = (float*)d_out;

    float *x, *tmp, *bqkv;
    __half *xch, *qkv, *attnc, *ffc, *w;
    cudaGetSymbolAddress((void**)&x,     g_x);
    cudaGetSymbolAddress((void**)&xch,   g_xch);
    cudaGetSymbolAddress((void**)&qkv,   g_qkv);
    cudaGetSymbolAddress((void**)&attnc, g_attnc);
    cudaGetSymbolAddress((void**)&tmp,   g_tmp);
    cudaGetSymbolAddress((void**)&ffc,   g_ffc);
    cudaGetSymbolAddress((void**)&w,     g_w);
    cudaGetSymbolAddress((void**)&bqkv,  g_bqkv);

    cudaFuncSetAttribute(gemm_h_kernel, cudaFuncAttributeMaxDynamicSharedMemorySize, GEMM_SMEM);

    cudaStream_t s2;
    cudaStreamCreateWithFlags(&s2, cudaStreamNonBlocking);
    cudaEvent_t eFork, eJoin;
    cudaEventCreateWithFlags(&eFork, cudaEventDisableTiming);
    cudaEventCreateWithFlags(&eJoin, cudaEventDisableTiming);

    // serial prologue on the origin stream
    prep_all_kernel<<<PREP_TILES, dim3(32, 8)>>>(Wq, Wk, Wv, Wo, W1, W2, Wf, w);
    cvt_bias_kernel<<<(Lz * QKVN) / 256, 256>>>(bq, bk, bv, bqkv);
    embed_kernel<<<Mz, 256>>>(ids, emb, x, xch);

    // fork
    cudaEventRecord(eFork, 0);
    cudaStreamWaitEvent(s2, eFork, 0);

    HalfCtx c = { x, xch, qkv, attnc, tmp, ffc, w, bqkv, out,
                  bo, ln1g, ln1b, ln2g, ln2b, b1, b2, bf, sp };

    run_half(0,  c, 0,  0);          // batches 0-1 on origin stream
    run_half(s2, c, MH, Bz / 2);     // batches 2-3 on s2

    // join
    cudaEventRecord(eJoin, s2);
    cudaStreamWaitEvent(0, eJoin, 0);
}